// round 13
// baseline (speedup 1.0000x reference)
#include <cuda_runtime.h>
#include <cuda_bf16.h>
#include <cstdint>

// ---------------------------------------------------------------------------
// Mamba block forward. R13: R12 exactly (865us verified) with the GEMM
// pipeline deepened 2 -> 3 stages (96KB smem, still 2 CTAs/SM via
// __launch_bounds__(256,2); R12 ncu: tensor=74.1%, DRAM=3.1% -> idle is
// cp.async-wait/barrier exposure, hidden by one extra stage in flight).
// B=2, L=2048, D_MODEL=1024, D_INNER=2048, D_STATE=16, DT_RANK=64, D_CONV=4
// ---------------------------------------------------------------------------

#define NTOK   4096
#define DMODEL 1024
#define DINNER 2048
#define DSTATE 16
#define DTRANK 64
#define XDBL   96
#define LSEQ   2048
#define NSLAB  4
#define OSLAB  4

// fp32 scratch
__device__ float g_xr[(size_t)NTOK * 4096];
__device__ float g_u[(size_t)NTOK * DINNER];
__device__ float g_xdblp[(size_t)NSLAB * NTOK * XDBL];
__device__ float g_xdbl[(size_t)NTOK * XDBL];
__device__ float g_delta[(size_t)NTOK * DINNER];
__device__ float g_ys[(size_t)NTOK * DINNER];
__device__ float g_outp[(size_t)OSLAB * NTOK * DMODEL];

// bf16 hi/lo scratch
__device__ __nv_bfloat16 g_xh[(size_t)NTOK * DMODEL],  g_xl[(size_t)NTOK * DMODEL];
__device__ __nv_bfloat16 g_wih[(size_t)4096 * DMODEL], g_wil[(size_t)4096 * DMODEL];
__device__ __nv_bfloat16 g_uh[(size_t)NTOK * DINNER],  g_ul[(size_t)NTOK * DINNER];
__device__ __nv_bfloat16 g_wxh[(size_t)XDBL * DINNER], g_wxl[(size_t)XDBL * DINNER];
__device__ __nv_bfloat16 g_xdh[(size_t)NTOK * XDBL],   g_xdl[(size_t)NTOK * XDBL];
__device__ __nv_bfloat16 g_wdh[(size_t)DINNER * DTRANK], g_wdl[(size_t)DINNER * DTRANK];
__device__ __nv_bfloat16 g_ygh[(size_t)NTOK * DINNER], g_ygl[(size_t)NTOK * DINNER];
__device__ __nv_bfloat16 g_woh[(size_t)DMODEL * DINNER], g_wol[(size_t)DMODEL * DINNER];

__device__ __forceinline__ uint32_t smem_to_u32(const void* p) {
    uint32_t a;
    asm("{ .reg .u64 t; cvta.to.shared.u64 t, %1; cvt.u32.u64 %0, t; }"
        : "=r"(a) : "l"(p));
    return a;
}

#define CP_ASYNC16(dst, src) \
    asm volatile("cp.async.cg.shared.global [%0], [%1], 16;" :: "r"(dst), "l"(src))
#define CP_COMMIT() asm volatile("cp.async.commit_group;" ::: "memory")
#define CP_WAIT0()  asm volatile("cp.async.wait_group 0;" ::: "memory")
#define CP_WAIT1()  asm volatile("cp.async.wait_group 1;" ::: "memory")
#define CP_WAIT2()  asm volatile("cp.async.wait_group 2;" ::: "memory")

#define LDSM_X4(r0, r1, r2, r3, a) \
    asm volatile("ldmatrix.sync.aligned.m8n8.x4.shared.b16 {%0,%1,%2,%3}, [%4];" \
        : "=r"(r0), "=r"(r1), "=r"(r2), "=r"(r3) : "r"(a))

#define MMA_BF16(d, a, b) \
    asm volatile("mma.sync.aligned.m16n8k16.row.col.f32.bf16.bf16.f32 " \
        "{%0,%1,%2,%3}, {%4,%5,%6,%7}, {%8,%9}, {%0,%1,%2,%3};" \
        : "+f"((d)[0]), "+f"((d)[1]), "+f"((d)[2]), "+f"((d)[3]) \
        : "r"((a)[0]), "r"((a)[1]), "r"((a)[2]), "r"((a)[3]), \
          "r"((b)[0]), "r"((b)[1]))

__device__ __forceinline__ uint32_t swoff(int row, int c) {
    return (uint32_t)(row * 64 + ((c ^ ((row >> 1) & 3)) << 4));
}

__device__ __forceinline__ float softplus_f(float v) {
    if (v > 20.f)  return v;
    if (v < -20.f) return __expf(v);
    return log1pf(__expf(v));
}

// ===========================================================================
// 128x128 NT GEMM, bf16 hi/lo split, 3-stage cp.async, 2 CTAs/SM.
// EPI: 0 = store, 1 = softplus(v+bias[col]) store,
//      2 = splitK slab: blockIdx.z = k-slice, store to C + z*sstride.
// ===========================================================================
#define GSTAGE 32768
#define GEMM_SMEM (3 * GSTAGE)

template <int EPI>
__global__ __launch_bounds__(256, 2) void gemm_mma(
    const __nv_bfloat16* __restrict__ Ah, const __nv_bfloat16* __restrict__ Al,
    const __nv_bfloat16* __restrict__ Bh, const __nv_bfloat16* __restrict__ Bl,
    float* __restrict__ C, const float* __restrict__ bias,
    int N, int Kc, int lda, int ldb, int ldc, int sstride)
{
    extern __shared__ char smem[];
    const uint32_t sb = smem_to_u32(smem);
    const int tid  = threadIdx.x;
    const int wid  = tid >> 5;
    const int lane = tid & 31;
    const int wm = wid & 1;
    const int wn = wid >> 1;
    const int row0 = blockIdx.y * 128;
    const int col0 = blockIdx.x * 128;
    const int kstart = (EPI == 2) ? blockIdx.z * Kc : 0;
    if (EPI == 2) C += (size_t)blockIdx.z * sstride;

    const int lr = tid >> 2;
    const int lc = tid & 3;

    const int a_rl = lane & 15;
    const int a_kc = lane >> 4;
    const int b_rl = (lane & 7) + ((lane >> 4) << 3);
    const int b_kc = (lane >> 3) & 1;

    float acc[4][4][4];
#pragma unroll
    for (int i = 0; i < 4; ++i)
#pragma unroll
        for (int j = 0; j < 4; ++j)
#pragma unroll
            for (int q = 0; q < 4; ++q) acc[i][j][q] = 0.f;

    const int nch = Kc >> 5;

    auto load_stage = [&](int stage, int k0) {
#pragma unroll
        for (int i = 0; i < 8; ++i) {
            const int tile = i >> 1;
            const int r = ((i & 1) << 6) + lr;
            const uint32_t dst = sb + stage * GSTAGE + tile * 8192 + swoff(r, lc);
            const __nv_bfloat16* src;
            if (tile < 2) {
                const __nv_bfloat16* base = tile ? Al : Ah;
                src = base + (size_t)(row0 + r) * lda + k0 + lc * 8;
            } else {
                int gn = col0 + r; if (gn >= N) gn = N - 1;
                const __nv_bfloat16* base = (tile == 2) ? Bh : Bl;
                src = base + (size_t)gn * ldb + k0 + lc * 8;
            }
            CP_ASYNC16(dst, src);
        }
    };

    // prologue: fill 2 of 3 stages
    load_stage(0, kstart); CP_COMMIT();
    if (nch > 1) { load_stage(1, kstart + 32); CP_COMMIT(); }

    for (int ch = 0; ch < nch; ++ch) {
        if (ch + 2 < nch) {
            load_stage((ch + 2) % 3, kstart + ((ch + 2) << 5));
            CP_COMMIT();
        }
        const int pend = (nch - ch - 1 < 2) ? (nch - ch - 1) : 2;
        if (pend == 2)      { CP_WAIT2(); }
        else if (pend == 1) { CP_WAIT1(); }
        else                { CP_WAIT0(); }
        __syncthreads();

        const uint32_t st = sb + (ch % 3) * GSTAGE;
#pragma unroll
        for (int ks = 0; ks < 2; ++ks) {
            uint32_t ah[4][4], al[4][4];
#pragma unroll
            for (int mt = 0; mt < 4; ++mt) {
                const int row = wm * 64 + mt * 16 + a_rl;
                const uint32_t ad = st + swoff(row, ks * 2 + a_kc);
                LDSM_X4(ah[mt][0], ah[mt][1], ah[mt][2], ah[mt][3], ad);
                LDSM_X4(al[mt][0], al[mt][1], al[mt][2], al[mt][3], ad + 8192);
            }
            uint32_t bh[2][4], bl[2][4];
#pragma unroll
            for (int p = 0; p < 2; ++p) {
                const int row = wn * 32 + p * 16 + b_rl;
                const uint32_t bd = st + 16384 + swoff(row, ks * 2 + b_kc);
                LDSM_X4(bh[p][0], bh[p][1], bh[p][2], bh[p][3], bd);
                LDSM_X4(bl[p][0], bl[p][1], bl[p][2], bl[p][3], bd + 8192);
            }
#pragma unroll
            for (int mt = 0; mt < 4; ++mt)
#pragma unroll
                for (int nt = 0; nt < 4; ++nt) {
                    uint32_t bfh[2] = { bh[nt >> 1][(nt & 1) * 2],
                                        bh[nt >> 1][(nt & 1) * 2 + 1] };
                    uint32_t bfl[2] = { bl[nt >> 1][(nt & 1) * 2],
                                        bl[nt >> 1][(nt & 1) * 2 + 1] };
                    MMA_BF16(acc[mt][nt], ah[mt], bfh);
                    MMA_BF16(acc[mt][nt], ah[mt], bfl);
                    MMA_BF16(acc[mt][nt], al[mt], bfh);
                }
        }
        __syncthreads();
    }

#pragma unroll
    for (int mt = 0; mt < 4; ++mt) {
        const int r = row0 + wm * 64 + mt * 16 + (lane >> 2);
#pragma unroll
        for (int nt = 0; nt < 4; ++nt) {
            const int cb = col0 + wn * 32 + nt * 8 + ((lane & 3) << 1);
            if (cb >= N) continue;
            if (EPI == 1) {
                const float b0 = bias[cb], b1 = bias[cb + 1];
                *(float2*)(C + (size_t)r * ldc + cb) = make_float2(
                    softplus_f(acc[mt][nt][0] + b0), softplus_f(acc[mt][nt][1] + b1));
                *(float2*)(C + (size_t)(r + 8) * ldc + cb) = make_float2(
                    softplus_f(acc[mt][nt][2] + b0), softplus_f(acc[mt][nt][3] + b1));
            } else {
                *(float2*)(C + (size_t)r * ldc + cb) =
                    make_float2(acc[mt][nt][0], acc[mt][nt][1]);
                *(float2*)(C + (size_t)(r + 8) * ldc + cb) =
                    make_float2(acc[mt][nt][2], acc[mt][nt][3]);
            }
        }
    }
}

// ---------------------------------------------------------------------------
__global__ __launch_bounds__(256) void cvt_split(
    const float4* __restrict__ src, __nv_bfloat162* __restrict__ hi,
    __nv_bfloat162* __restrict__ lo, int n4)
{
    int i = blockIdx.x * blockDim.x + threadIdx.x;
    if (i >= n4) return;
    float4 v = src[i];
    __nv_bfloat16 h0 = __float2bfloat16(v.x), h1 = __float2bfloat16(v.y);
    __nv_bfloat16 h2 = __float2bfloat16(v.z), h3 = __float2bfloat16(v.w);
    hi[2 * i]     = __halves2bfloat162(h0, h1);
    hi[2 * i + 1] = __halves2bfloat162(h2, h3);
    lo[2 * i]     = __halves2bfloat162(
        __float2bfloat16(v.x - __bfloat162float(h0)),
        __float2bfloat16(v.y - __bfloat162float(h1)));
    lo[2 * i + 1] = __halves2bfloat162(
        __float2bfloat16(v.z - __bfloat162float(h2)),
        __float2bfloat16(v.w - __bfloat162float(h3)));
}

// sum NSLAB splitK slabs -> fp32 xdbl + bf16 hi/lo
__global__ __launch_bounds__(256) void reduce_split_kernel(
    const float4* __restrict__ slabs, float4* __restrict__ xdbl,
    __nv_bfloat162* __restrict__ hi, __nv_bfloat162* __restrict__ lo, int n4)
{
    int i = blockIdx.x * blockDim.x + threadIdx.x;
    if (i >= n4) return;
    float4 v = slabs[i];
#pragma unroll
    for (int s = 1; s < NSLAB; ++s) {
        float4 w = slabs[(size_t)s * n4 + i];
        v.x += w.x; v.y += w.y; v.z += w.z; v.w += w.w;
    }
    xdbl[i] = v;
    __nv_bfloat16 h0 = __float2bfloat16(v.x), h1 = __float2bfloat16(v.y);
    __nv_bfloat16 h2 = __float2bfloat16(v.z), h3 = __float2bfloat16(v.w);
    hi[2 * i]     = __halves2bfloat162(h0, h1);
    hi[2 * i + 1] = __halves2bfloat162(h2, h3);
    lo[2 * i]     = __halves2bfloat162(
        __float2bfloat16(v.x - __bfloat162float(h0)),
        __float2bfloat16(v.y - __bfloat162float(h1)));
    lo[2 * i + 1] = __halves2bfloat162(
        __float2bfloat16(v.z - __bfloat162float(h2)),
        __float2bfloat16(v.w - __bfloat162float(h3)));
}

// sum OSLAB out_proj slabs -> final fp32 out
__global__ __launch_bounds__(256) void reduce_out_kernel(
    const float4* __restrict__ slabs, float4* __restrict__ out, int n4)
{
    int i = blockIdx.x * blockDim.x + threadIdx.x;
    if (i >= n4) return;
    float4 v = slabs[i];
#pragma unroll
    for (int s = 1; s < OSLAB; ++s) {
        float4 w = slabs[(size_t)s * n4 + i];
        v.x += w.x; v.y += w.y; v.z += w.z; v.w += w.w;
    }
    out[i] = v;
}

// causal dwconv(4) + bias + SiLU, 2 channels/thread (float2) — ncu-verified.
__global__ __launch_bounds__(256) void conv_silu_kernel(
    const float* __restrict__ xr, const float* __restrict__ cw,
    const float* __restrict__ cb, float* __restrict__ u,
    __nv_bfloat162* __restrict__ uh, __nv_bfloat162* __restrict__ ul)
{
    int idx = blockIdx.x * blockDim.x + threadIdx.x;
    if (idx >= NTOK * DINNER / 2) return;
    int dp = idx & (DINNER / 2 - 1);
    int d  = dp << 1;
    int m  = idx >> 10;
    int b  = m >> 11;
    int l  = m & (LSEQ - 1);

    float4 w0 = *(const float4*)(cw + d * 4);
    float4 w1 = *(const float4*)(cw + d * 4 + 4);
    float2 a = make_float2(cb[d], cb[d + 1]);
    int base = b << 11;
    const float* p = xr + (size_t)(base + l) * 4096 + d;
    float2 t;
    if (l >= 3) { t = *(const float2*)(p - 3 * 4096);
                  a.x = fmaf(t.x, w0.x, a.x); a.y = fmaf(t.y, w1.x, a.y); }
    if (l >= 2) { t = *(const float2*)(p - 2 * 4096);
                  a.x = fmaf(t.x, w0.y, a.x); a.y = fmaf(t.y, w1.y, a.y); }
    if (l >= 1) { t = *(const float2*)(p - 1 * 4096);
                  a.x = fmaf(t.x, w0.z, a.x); a.y = fmaf(t.y, w1.z, a.y); }
    t = *(const float2*)p;
    a.x = fmaf(t.x, w0.w, a.x); a.y = fmaf(t.y, w1.w, a.y);

    float vx = a.x / (1.f + __expf(-a.x));
    float vy = a.y / (1.f + __expf(-a.y));
    *(float2*)(u + (size_t)idx * 2) = make_float2(vx, vy);
    __nv_bfloat16 hx = __float2bfloat16(vx), hy = __float2bfloat16(vy);
    uh[idx] = __halves2bfloat162(hx, hy);
    ul[idx] = __halves2bfloat162(
        __float2bfloat16(vx - __bfloat162float(hx)),
        __float2bfloat16(vy - __bfloat162float(hy)));
}

// ---------------------------------------------------------------------------
// selective scan — EXACT R7/R10/R11/R12 version. Do not touch w/o a profile.
// ---------------------------------------------------------------------------
__global__ __launch_bounds__(256) void scan_kernel(
    const float* __restrict__ delta, const float* __restrict__ u,
    const float* __restrict__ xdbl, const float* __restrict__ A_log,
    float* __restrict__ ys)
{
    int gid = blockIdx.x * blockDim.x + threadIdx.x;
    if (gid >= NTOK * DSTATE) return;
    int n = gid & (DSTATE - 1);
    int ch = gid >> 4;
    int b = ch >> 11;
    int d = ch & (DINNER - 1);

    const float A = -__expf(A_log[d * DSTATE + n]);
    const size_t chanBase = (size_t)(b << 11) * DINNER + d;
    const float* dp = delta + chanBase;
    const float* up = u + chanBase;
    const float* xd = xdbl + (size_t)(b << 11) * XDBL;
    float* yp = ys + chanBase;

    float h = 0.f;
    for (int l = 0; l < LSEQ; ++l) {
        float dl = dp[(size_t)l * DINNER];
        float ul = up[(size_t)l * DINNER];
        float Bv = xd[l * XDBL + DTRANK + n];
        float Cv = xd[l * XDBL + DTRANK + DSTATE + n];
        float dA = __expf(dl * A);
        h = fmaf(dA, h, dl * ul * Bv);
        float v = h * Cv;
#pragma unroll
        for (int off = 8; off; off >>= 1)
            v += __shfl_xor_sync(0xffffffffu, v, off, 16);
        if (n == 0) yp[(size_t)l * DINNER] = v;
    }
}

// y = (ys + u*D) * silu(res), 2 channels/thread; emits bf16 hi/lo.
__global__ __launch_bounds__(256) void gate_kernel(
    const float* __restrict__ ys, const float* __restrict__ u,
    const float* __restrict__ Dp, const float* __restrict__ xr,
    __nv_bfloat162* __restrict__ ygh, __nv_bfloat162* __restrict__ ygl)
{
    int idx = blockIdx.x * blockDim.x + threadIdx.x;
    if (idx >= NTOK * DINNER / 2) return;
    int dpair = idx & (DINNER / 2 - 1);
    int d = dpair << 1;
    int m = idx >> 10;
    float2 res = *(const float2*)(xr + (size_t)m * 4096 + DINNER + d);
    float2 yv  = *(const float2*)(ys + (size_t)idx * 2);
    float2 uv  = *(const float2*)(u + (size_t)idx * 2);
    float2 Dv  = *(const float2*)(Dp + d);
    float gx = res.x / (1.f + __expf(-res.x));
    float gy = res.y / (1.f + __expf(-res.y));
    float vx = (yv.x + uv.x * Dv.x) * gx;
    float vy = (yv.y + uv.y * Dv.y) * gy;
    __nv_bfloat16 hx = __float2bfloat16(vx), hy = __float2bfloat16(vy);
    ygh[idx] = __halves2bfloat162(hx, hy);
    ygl[idx] = __halves2bfloat162(
        __float2bfloat16(vx - __bfloat162float(hx)),
        __float2bfloat16(vy - __bfloat162float(hy)));
}

// ---------------------------------------------------------------------------
extern "C" void kernel_launch(void* const* d_in, const int* in_sizes, int n_in,
                              void* d_out, int out_size)
{
    const float* x        = (const float*)d_in[0];
    const float* conv_w   = (const float*)d_in[2];
    const float* conv_b   = (const float*)d_in[3];
    const float* dtproj_b = (const float*)d_in[6];
    const float* A_log    = (const float*)d_in[7];
    const float* Dvec     = (const float*)d_in[8];
    float* out            = (float*)d_out;

    float *xr, *u, *xdblp, *xdbl, *delta, *ys, *outp;
    cudaGetSymbolAddress((void**)&xr,    g_xr);
    cudaGetSymbolAddress((void**)&u,     g_u);
    cudaGetSymbolAddress((void**)&xdblp, g_xdblp);
    cudaGetSymbolAddress((void**)&xdbl,  g_xdbl);
    cudaGetSymbolAddress((void**)&delta, g_delta);
    cudaGetSymbolAddress((void**)&ys,    g_ys);
    cudaGetSymbolAddress((void**)&outp,  g_outp);

    __nv_bfloat16 *xh, *xl, *wih, *wil, *uh, *ul, *wxh, *wxl;
    __nv_bfloat16 *xdh, *xdl, *wdh, *wdl, *ygh, *ygl, *woh, *wol;
    cudaGetSymbolAddress((void**)&xh,  g_xh);  cudaGetSymbolAddress((void**)&xl,  g_xl);
    cudaGetSymbolAddress((void**)&wih, g_wih); cudaGetSymbolAddress((void**)&wil, g_wil);
    cudaGetSymbolAddress((void**)&uh,  g_uh);  cudaGetSymbolAddress((void**)&ul,  g_ul);
    cudaGetSymbolAddress((void**)&wxh, g_wxh); cudaGetSymbolAddress((void**)&wxl, g_wxl);
    cudaGetSymbolAddress((void**)&xdh, g_xdh); cudaGetSymbolAddress((void**)&xdl, g_xdl);
    cudaGetSymbolAddress((void**)&wdh, g_wdh); cudaGetSymbolAddress((void**)&wdl, g_wdl);
    cudaGetSymbolAddress((void**)&ygh, g_ygh); cudaGetSymbolAddress((void**)&ygl, g_ygl);
    cudaGetSymbolAddress((void**)&woh, g_woh); cudaGetSymbolAddress((void**)&wol, g_wol);

    cudaFuncSetAttribute(gemm_mma<0>, cudaFuncAttributeMaxDynamicSharedMemorySize, GEMM_SMEM);
    cudaFuncSetAttribute(gemm_mma<1>, cudaFuncAttributeMaxDynamicSharedMemorySize, GEMM_SMEM);
    cudaFuncSetAttribute(gemm_mma<2>, cudaFuncAttributeMaxDynamicSharedMemorySize, GEMM_SMEM);

    const int EW2 = NTOK * DINNER / 2;
#define CVT(src, hi, lo, n) \
    cvt_split<<<(n) / 1024, 256>>>((const float4*)(src), (__nv_bfloat162*)(hi), \
                                   (__nv_bfloat162*)(lo), (n) / 4)

    // launches 0-2: conversions — keeps in_proj gemm at profiled index 3
    CVT(x, xh, xl, NTOK * DMODEL);
    CVT(d_in[1], wih, wil, 4096 * DMODEL);
    CVT(d_in[4], wxh, wxl, XDBL * DINNER);
    // launch 3 (PROFILED): in_proj xr = x @ in_w^T  (4096 x 4096 x 1024)
    gemm_mma<0><<<dim3(32, 32), 256, GEMM_SMEM>>>(
        xh, xl, wih, wil, xr, nullptr, 4096, DMODEL, DMODEL, DMODEL, 4096, 0);
    // conv + silu -> u, uh, ul
    conv_silu_kernel<<<EW2 / 256, 256>>>(xr, conv_w, conv_b, u,
                                         (__nv_bfloat162*)uh, (__nv_bfloat162*)ul);
    // x_proj splitK(4) slabs (4096 x 96 x 2048), grid (1,32,NSLAB)
    gemm_mma<2><<<dim3(1, 32, NSLAB), 256, GEMM_SMEM>>>(
        uh, ul, wxh, wxl, xdblp, nullptr, XDBL, DINNER / NSLAB,
        DINNER, DINNER, XDBL, NTOK * XDBL);
    reduce_split_kernel<<<(NTOK * XDBL / 4 + 255) / 256, 256>>>(
        (const float4*)xdblp, (float4*)xdbl,
        (__nv_bfloat162*)xdh, (__nv_bfloat162*)xdl, NTOK * XDBL / 4);
    // dt_proj + bias + softplus: delta (4096 x 2048 x 64)
    CVT(d_in[5], wdh, wdl, DINNER * DTRANK);
    gemm_mma<1><<<dim3(16, 32), 256, GEMM_SMEM>>>(
        xdh, xdl, wdh, wdl, delta, dtproj_b, DINNER, DTRANK, XDBL, DTRANK, DINNER, 0);
    // scan (exact)
    scan_kernel<<<(NTOK * DSTATE) / 256, 256>>>(delta, u, xdbl, A_log, ys);
    // gate -> ygh/ygl
    gate_kernel<<<EW2 / 256, 256>>>(ys, u, Dvec, xr,
                                    (__nv_bfloat162*)ygh, (__nv_bfloat162*)ygl);
    // out_proj splitK(4) slabs: (4096 x 1024 x 2048), grid (8,32,OSLAB)
    CVT(d_in[9], woh, wol, DMODEL * DINNER);
    gemm_mma<2><<<dim3(8, 32, OSLAB), 256, GEMM_SMEM>>>(
        ygh, ygl, woh, wol, outp, nullptr, DMODEL, DINNER / OSLAB,
        DINNER, DINNER, DMODEL, NTOK * DMODEL);
    reduce_out_kernel<<<(NTOK * DMODEL / 4 + 255) / 256, 256>>>(
        (const float4*)outp, (float4*)out, NTOK * DMODEL / 4);
#undef CVT
}

// round 14
// speedup vs baseline: 1.0363x; 1.0363x over previous
#include <cuda_runtime.h>
#include <cuda_bf16.h>
#include <cstdint>

// ---------------------------------------------------------------------------
// Mamba block forward. R14: GEMM reverted to R12 2-stage (865us verified;
// R13 3-stage was neutral-negative) + scan parallelized over L via linear
// chunk decomposition (8 chunks: pass1 local scans, pass2 carry combine,
// pass3 replay+emit). Scan was ~300us latency-bound at 14 warps/SM.
// B=2, L=2048, D_MODEL=1024, D_INNER=2048, D_STATE=16, DT_RANK=64, D_CONV=4
// ---------------------------------------------------------------------------

#define NTOK   4096
#define DMODEL 1024
#define DINNER 2048
#define DSTATE 16
#define DTRANK 64
#define XDBL   96
#define LSEQ   2048
#define NSLAB  4
#define OSLAB  4
#define NCH    8
#define CLEN   (LSEQ / NCH)          // 256
#define NSCAN  (NTOK * DSTATE * NCH) // 524288

// fp32 scratch
__device__ float g_xr[(size_t)NTOK * 4096];
__device__ float g_u[(size_t)NTOK * DINNER];
__device__ float g_xdblp[(size_t)NSLAB * NTOK * XDBL];
__device__ float g_xdbl[(size_t)NTOK * XDBL];
__device__ float g_delta[(size_t)NTOK * DINNER];
__device__ float g_ys[(size_t)NTOK * DINNER];
__device__ float g_outp[(size_t)OSLAB * NTOK * DMODEL];
__device__ float g_sA[NSCAN], g_sS[NSCAN], g_hc[NSCAN];

// bf16 hi/lo scratch
__device__ __nv_bfloat16 g_xh[(size_t)NTOK * DMODEL],  g_xl[(size_t)NTOK * DMODEL];
__device__ __nv_bfloat16 g_wih[(size_t)4096 * DMODEL], g_wil[(size_t)4096 * DMODEL];
__device__ __nv_bfloat16 g_uh[(size_t)NTOK * DINNER],  g_ul[(size_t)NTOK * DINNER];
__device__ __nv_bfloat16 g_wxh[(size_t)XDBL * DINNER], g_wxl[(size_t)XDBL * DINNER];
__device__ __nv_bfloat16 g_xdh[(size_t)NTOK * XDBL],   g_xdl[(size_t)NTOK * XDBL];
__device__ __nv_bfloat16 g_wdh[(size_t)DINNER * DTRANK], g_wdl[(size_t)DINNER * DTRANK];
__device__ __nv_bfloat16 g_ygh[(size_t)NTOK * DINNER], g_ygl[(size_t)NTOK * DINNER];
__device__ __nv_bfloat16 g_woh[(size_t)DMODEL * DINNER], g_wol[(size_t)DMODEL * DINNER];

__device__ __forceinline__ uint32_t smem_to_u32(const void* p) {
    uint32_t a;
    asm("{ .reg .u64 t; cvta.to.shared.u64 t, %1; cvt.u32.u64 %0, t; }"
        : "=r"(a) : "l"(p));
    return a;
}

#define CP_ASYNC16(dst, src) \
    asm volatile("cp.async.cg.shared.global [%0], [%1], 16;" :: "r"(dst), "l"(src))
#define CP_COMMIT() asm volatile("cp.async.commit_group;" ::: "memory")
#define CP_WAIT0()  asm volatile("cp.async.wait_group 0;" ::: "memory")
#define CP_WAIT1()  asm volatile("cp.async.wait_group 1;" ::: "memory")

#define LDSM_X4(r0, r1, r2, r3, a) \
    asm volatile("ldmatrix.sync.aligned.m8n8.x4.shared.b16 {%0,%1,%2,%3}, [%4];" \
        : "=r"(r0), "=r"(r1), "=r"(r2), "=r"(r3) : "r"(a))

#define MMA_BF16(d, a, b) \
    asm volatile("mma.sync.aligned.m16n8k16.row.col.f32.bf16.bf16.f32 " \
        "{%0,%1,%2,%3}, {%4,%5,%6,%7}, {%8,%9}, {%0,%1,%2,%3};" \
        : "+f"((d)[0]), "+f"((d)[1]), "+f"((d)[2]), "+f"((d)[3]) \
        : "r"((a)[0]), "r"((a)[1]), "r"((a)[2]), "r"((a)[3]), \
          "r"((b)[0]), "r"((b)[1]))

__device__ __forceinline__ uint32_t swoff(int row, int c) {
    return (uint32_t)(row * 64 + ((c ^ ((row >> 1) & 3)) << 4));
}

__device__ __forceinline__ float softplus_f(float v) {
    if (v > 20.f)  return v;
    if (v < -20.f) return __expf(v);
    return log1pf(__expf(v));
}

// ===========================================================================
// 128x128 NT GEMM, bf16 hi/lo split, 2-stage cp.async, 2 CTAs/SM (R12 exact).
// EPI: 0 = store, 1 = softplus(v+bias[col]) store,
//      2 = splitK slab: blockIdx.z = k-slice, store to C + z*sstride.
// ===========================================================================
#define GSTAGE 32768
#define GEMM_SMEM (2 * GSTAGE)

template <int EPI>
__global__ __launch_bounds__(256, 2) void gemm_mma(
    const __nv_bfloat16* __restrict__ Ah, const __nv_bfloat16* __restrict__ Al,
    const __nv_bfloat16* __restrict__ Bh, const __nv_bfloat16* __restrict__ Bl,
    float* __restrict__ C, const float* __restrict__ bias,
    int N, int Kc, int lda, int ldb, int ldc, int sstride)
{
    extern __shared__ char smem[];
    const uint32_t sb = smem_to_u32(smem);
    const int tid  = threadIdx.x;
    const int wid  = tid >> 5;
    const int lane = tid & 31;
    const int wm = wid & 1;
    const int wn = wid >> 1;
    const int row0 = blockIdx.y * 128;
    const int col0 = blockIdx.x * 128;
    const int kstart = (EPI == 2) ? blockIdx.z * Kc : 0;
    if (EPI == 2) C += (size_t)blockIdx.z * sstride;

    const int lr = tid >> 2;
    const int lc = tid & 3;

    const int a_rl = lane & 15;
    const int a_kc = lane >> 4;
    const int b_rl = (lane & 7) + ((lane >> 4) << 3);
    const int b_kc = (lane >> 3) & 1;

    float acc[4][4][4];
#pragma unroll
    for (int i = 0; i < 4; ++i)
#pragma unroll
        for (int j = 0; j < 4; ++j)
#pragma unroll
            for (int q = 0; q < 4; ++q) acc[i][j][q] = 0.f;

    const int nch = Kc >> 5;

    auto load_stage = [&](int stage, int k0) {
#pragma unroll
        for (int i = 0; i < 8; ++i) {
            const int tile = i >> 1;
            const int r = ((i & 1) << 6) + lr;
            const uint32_t dst = sb + stage * GSTAGE + tile * 8192 + swoff(r, lc);
            const __nv_bfloat16* src;
            if (tile < 2) {
                const __nv_bfloat16* base = tile ? Al : Ah;
                src = base + (size_t)(row0 + r) * lda + k0 + lc * 8;
            } else {
                int gn = col0 + r; if (gn >= N) gn = N - 1;
                const __nv_bfloat16* base = (tile == 2) ? Bh : Bl;
                src = base + (size_t)gn * ldb + k0 + lc * 8;
            }
            CP_ASYNC16(dst, src);
        }
    };

    load_stage(0, kstart);
    CP_COMMIT();

    for (int ch = 0; ch < nch; ++ch) {
        if (ch + 1 < nch) {
            load_stage((ch + 1) & 1, kstart + ((ch + 1) << 5));
            CP_COMMIT();
            CP_WAIT1();
        } else {
            CP_WAIT0();
        }
        __syncthreads();

        const uint32_t st = sb + (ch & 1) * GSTAGE;
#pragma unroll
        for (int ks = 0; ks < 2; ++ks) {
            uint32_t ah[4][4], al[4][4];
#pragma unroll
            for (int mt = 0; mt < 4; ++mt) {
                const int row = wm * 64 + mt * 16 + a_rl;
                const uint32_t ad = st + swoff(row, ks * 2 + a_kc);
                LDSM_X4(ah[mt][0], ah[mt][1], ah[mt][2], ah[mt][3], ad);
                LDSM_X4(al[mt][0], al[mt][1], al[mt][2], al[mt][3], ad + 8192);
            }
            uint32_t bh[2][4], bl[2][4];
#pragma unroll
            for (int p = 0; p < 2; ++p) {
                const int row = wn * 32 + p * 16 + b_rl;
                const uint32_t bd = st + 16384 + swoff(row, ks * 2 + b_kc);
                LDSM_X4(bh[p][0], bh[p][1], bh[p][2], bh[p][3], bd);
                LDSM_X4(bl[p][0], bl[p][1], bl[p][2], bl[p][3], bd + 8192);
            }
#pragma unroll
            for (int mt = 0; mt < 4; ++mt)
#pragma unroll
                for (int nt = 0; nt < 4; ++nt) {
                    uint32_t bfh[2] = { bh[nt >> 1][(nt & 1) * 2],
                                        bh[nt >> 1][(nt & 1) * 2 + 1] };
                    uint32_t bfl[2] = { bl[nt >> 1][(nt & 1) * 2],
                                        bl[nt >> 1][(nt & 1) * 2 + 1] };
                    MMA_BF16(acc[mt][nt], ah[mt], bfh);
                    MMA_BF16(acc[mt][nt], ah[mt], bfl);
                    MMA_BF16(acc[mt][nt], al[mt], bfh);
                }
        }
        __syncthreads();
    }

#pragma unroll
    for (int mt = 0; mt < 4; ++mt) {
        const int r = row0 + wm * 64 + mt * 16 + (lane >> 2);
#pragma unroll
        for (int nt = 0; nt < 4; ++nt) {
            const int cb = col0 + wn * 32 + nt * 8 + ((lane & 3) << 1);
            if (cb >= N) continue;
            if (EPI == 1) {
                const float b0 = bias[cb], b1 = bias[cb + 1];
                *(float2*)(C + (size_t)r * ldc + cb) = make_float2(
                    softplus_f(acc[mt][nt][0] + b0), softplus_f(acc[mt][nt][1] + b1));
                *(float2*)(C + (size_t)(r + 8) * ldc + cb) = make_float2(
                    softplus_f(acc[mt][nt][2] + b0), softplus_f(acc[mt][nt][3] + b1));
            } else {
                *(float2*)(C + (size_t)r * ldc + cb) =
                    make_float2(acc[mt][nt][0], acc[mt][nt][1]);
                *(float2*)(C + (size_t)(r + 8) * ldc + cb) =
                    make_float2(acc[mt][nt][2], acc[mt][nt][3]);
            }
        }
    }
}

// ---------------------------------------------------------------------------
__global__ __launch_bounds__(256) void cvt_split(
    const float4* __restrict__ src, __nv_bfloat162* __restrict__ hi,
    __nv_bfloat162* __restrict__ lo, int n4)
{
    int i = blockIdx.x * blockDim.x + threadIdx.x;
    if (i >= n4) return;
    float4 v = src[i];
    __nv_bfloat16 h0 = __float2bfloat16(v.x), h1 = __float2bfloat16(v.y);
    __nv_bfloat16 h2 = __float2bfloat16(v.z), h3 = __float2bfloat16(v.w);
    hi[2 * i]     = __halves2bfloat162(h0, h1);
    hi[2 * i + 1] = __halves2bfloat162(h2, h3);
    lo[2 * i]     = __halves2bfloat162(
        __float2bfloat16(v.x - __bfloat162float(h0)),
        __float2bfloat16(v.y - __bfloat162float(h1)));
    lo[2 * i + 1] = __halves2bfloat162(
        __float2bfloat16(v.z - __bfloat162float(h2)),
        __float2bfloat16(v.w - __bfloat162float(h3)));
}

// sum NSLAB splitK slabs -> fp32 xdbl + bf16 hi/lo
__global__ __launch_bounds__(256) void reduce_split_kernel(
    const float4* __restrict__ slabs, float4* __restrict__ xdbl,
    __nv_bfloat162* __restrict__ hi, __nv_bfloat162* __restrict__ lo, int n4)
{
    int i = blockIdx.x * blockDim.x + threadIdx.x;
    if (i >= n4) return;
    float4 v = slabs[i];
#pragma unroll
    for (int s = 1; s < NSLAB; ++s) {
        float4 w = slabs[(size_t)s * n4 + i];
        v.x += w.x; v.y += w.y; v.z += w.z; v.w += w.w;
    }
    xdbl[i] = v;
    __nv_bfloat16 h0 = __float2bfloat16(v.x), h1 = __float2bfloat16(v.y);
    __nv_bfloat16 h2 = __float2bfloat16(v.z), h3 = __float2bfloat16(v.w);
    hi[2 * i]     = __halves2bfloat162(h0, h1);
    hi[2 * i + 1] = __halves2bfloat162(h2, h3);
    lo[2 * i]     = __halves2bfloat162(
        __float2bfloat16(v.x - __bfloat162float(h0)),
        __float2bfloat16(v.y - __bfloat162float(h1)));
    lo[2 * i + 1] = __halves2bfloat162(
        __float2bfloat16(v.z - __bfloat162float(h2)),
        __float2bfloat16(v.w - __bfloat162float(h3)));
}

// sum OSLAB out_proj slabs -> final fp32 out
__global__ __launch_bounds__(256) void reduce_out_kernel(
    const float4* __restrict__ slabs, float4* __restrict__ out, int n4)
{
    int i = blockIdx.x * blockDim.x + threadIdx.x;
    if (i >= n4) return;
    float4 v = slabs[i];
#pragma unroll
    for (int s = 1; s < OSLAB; ++s) {
        float4 w = slabs[(size_t)s * n4 + i];
        v.x += w.x; v.y += w.y; v.z += w.z; v.w += w.w;
    }
    out[i] = v;
}

// causal dwconv(4) + bias + SiLU, 2 channels/thread (float2) — ncu-verified.
__global__ __launch_bounds__(256) void conv_silu_kernel(
    const float* __restrict__ xr, const float* __restrict__ cw,
    const float* __restrict__ cb, float* __restrict__ u,
    __nv_bfloat162* __restrict__ uh, __nv_bfloat162* __restrict__ ul)
{
    int idx = blockIdx.x * blockDim.x + threadIdx.x;
    if (idx >= NTOK * DINNER / 2) return;
    int dp = idx & (DINNER / 2 - 1);
    int d  = dp << 1;
    int m  = idx >> 10;
    int b  = m >> 11;
    int l  = m & (LSEQ - 1);

    float4 w0 = *(const float4*)(cw + d * 4);
    float4 w1 = *(const float4*)(cw + d * 4 + 4);
    float2 a = make_float2(cb[d], cb[d + 1]);
    int base = b << 11;
    const float* p = xr + (size_t)(base + l) * 4096 + d;
    float2 t;
    if (l >= 3) { t = *(const float2*)(p - 3 * 4096);
                  a.x = fmaf(t.x, w0.x, a.x); a.y = fmaf(t.y, w1.x, a.y); }
    if (l >= 2) { t = *(const float2*)(p - 2 * 4096);
                  a.x = fmaf(t.x, w0.y, a.x); a.y = fmaf(t.y, w1.y, a.y); }
    if (l >= 1) { t = *(const float2*)(p - 1 * 4096);
                  a.x = fmaf(t.x, w0.z, a.x); a.y = fmaf(t.y, w1.z, a.y); }
    t = *(const float2*)p;
    a.x = fmaf(t.x, w0.w, a.x); a.y = fmaf(t.y, w1.w, a.y);

    float vx = a.x / (1.f + __expf(-a.x));
    float vy = a.y / (1.f + __expf(-a.y));
    *(float2*)(u + (size_t)idx * 2) = make_float2(vx, vy);
    __nv_bfloat16 hx = __float2bfloat16(vx), hy = __float2bfloat16(vy);
    uh[idx] = __halves2bfloat162(hx, hy);
    ul[idx] = __halves2bfloat162(
        __float2bfloat16(vx - __bfloat162float(hx)),
        __float2bfloat16(vy - __bfloat162float(hy)));
}

// ---------------------------------------------------------------------------
// Chunked parallel scan over L (linear recurrence decomposition).
// gid layout: bits [0:4)=n, [4:16)=channel (b,d), [16:19)=chunk c.
// ---------------------------------------------------------------------------
__global__ __launch_bounds__(256) void scan_pass1(
    const float* __restrict__ delta, const float* __restrict__ u,
    const float* __restrict__ xdbl, const float* __restrict__ A_log,
    float* __restrict__ sA, float* __restrict__ sS)
{
    int gid = blockIdx.x * blockDim.x + threadIdx.x;   // 0..NSCAN-1
    int n  = gid & (DSTATE - 1);
    int ch = (gid >> 4) & 4095;
    int c  = gid >> 16;
    int b = ch >> 11, d = ch & (DINNER - 1);

    const float A = -__expf(A_log[d * DSTATE + n]);
    const size_t chanBase = (size_t)(b << 11) * DINNER + d;
    const float* dp = delta + chanBase;
    const float* up = u + chanBase;
    const float* xd = xdbl + (size_t)(b << 11) * XDBL;

    float a = 1.f, h = 0.f;
    const int l0 = c * CLEN;
    for (int i = 0; i < CLEN; ++i) {
        const int l = l0 + i;
        float dl = dp[(size_t)l * DINNER];
        float ul = up[(size_t)l * DINNER];
        float Bv = xd[l * XDBL + DTRANK + n];
        float dA = __expf(dl * A);
        h = fmaf(dA, h, dl * ul * Bv);
        a *= dA;
    }
    sA[gid] = a;
    sS[gid] = h;
}

__global__ __launch_bounds__(256) void scan_pass2(
    const float* __restrict__ sA, const float* __restrict__ sS,
    float* __restrict__ hcar)
{
    int gid = blockIdx.x * blockDim.x + threadIdx.x;   // 0..65535 (ch,n)
    float hc = 0.f;
#pragma unroll
    for (int c = 0; c < NCH; ++c) {
        int idx = (c << 16) | gid;
        hcar[idx] = hc;
        hc = fmaf(sA[idx], hc, sS[idx]);
    }
}

__global__ __launch_bounds__(256) void scan_pass3(
    const float* __restrict__ delta, const float* __restrict__ u,
    const float* __restrict__ xdbl, const float* __restrict__ A_log,
    const float* __restrict__ hcar, float* __restrict__ ys)
{
    int gid = blockIdx.x * blockDim.x + threadIdx.x;
    int n  = gid & (DSTATE - 1);
    int ch = (gid >> 4) & 4095;
    int c  = gid >> 16;
    int b = ch >> 11, d = ch & (DINNER - 1);

    const float A = -__expf(A_log[d * DSTATE + n]);
    const size_t chanBase = (size_t)(b << 11) * DINNER + d;
    const float* dp = delta + chanBase;
    const float* up = u + chanBase;
    const float* xd = xdbl + (size_t)(b << 11) * XDBL;
    float* yp = ys + chanBase;

    float h = hcar[gid];
    const int l0 = c * CLEN;
    for (int i = 0; i < CLEN; ++i) {
        const int l = l0 + i;
        float dl = dp[(size_t)l * DINNER];
        float ul = up[(size_t)l * DINNER];
        float Bv = xd[l * XDBL + DTRANK + n];
        float Cv = xd[l * XDBL + DTRANK + DSTATE + n];
        float dA = __expf(dl * A);
        h = fmaf(dA, h, dl * ul * Bv);
        float v = h * Cv;
#pragma unroll
        for (int off = 8; off; off >>= 1)
            v += __shfl_xor_sync(0xffffffffu, v, off, 16);
        if (n == 0) yp[(size_t)l * DINNER] = v;
    }
}

// y = (ys + u*D) * silu(res), 2 channels/thread; emits bf16 hi/lo.
__global__ __launch_bounds__(256) void gate_kernel(
    const float* __restrict__ ys, const float* __restrict__ u,
    const float* __restrict__ Dp, const float* __restrict__ xr,
    __nv_bfloat162* __restrict__ ygh, __nv_bfloat162* __restrict__ ygl)
{
    int idx = blockIdx.x * blockDim.x + threadIdx.x;
    if (idx >= NTOK * DINNER / 2) return;
    int dpair = idx & (DINNER / 2 - 1);
    int d = dpair << 1;
    int m = idx >> 10;
    float2 res = *(const float2*)(xr + (size_t)m * 4096 + DINNER + d);
    float2 yv  = *(const float2*)(ys + (size_t)idx * 2);
    float2 uv  = *(const float2*)(u + (size_t)idx * 2);
    float2 Dv  = *(const float2*)(Dp + d);
    float gx = res.x / (1.f + __expf(-res.x));
    float gy = res.y / (1.f + __expf(-res.y));
    float vx = (yv.x + uv.x * Dv.x) * gx;
    float vy = (yv.y + uv.y * Dv.y) * gy;
    __nv_bfloat16 hx = __float2bfloat16(vx), hy = __float2bfloat16(vy);
    ygh[idx] = __halves2bfloat162(hx, hy);
    ygl[idx] = __halves2bfloat162(
        __float2bfloat16(vx - __bfloat162float(hx)),
        __float2bfloat16(vy - __bfloat162float(hy)));
}

// ---------------------------------------------------------------------------
extern "C" void kernel_launch(void* const* d_in, const int* in_sizes, int n_in,
                              void* d_out, int out_size)
{
    const float* x        = (const float*)d_in[0];
    const float* conv_w   = (const float*)d_in[2];
    const float* conv_b   = (const float*)d_in[3];
    const float* dtproj_b = (const float*)d_in[6];
    const float* A_log    = (const float*)d_in[7];
    const float* Dvec     = (const float*)d_in[8];
    float* out            = (float*)d_out;

    float *xr, *u, *xdblp, *xdbl, *delta, *ys, *outp, *sA, *sS, *hc;
    cudaGetSymbolAddress((void**)&xr,    g_xr);
    cudaGetSymbolAddress((void**)&u,     g_u);
    cudaGetSymbolAddress((void**)&xdblp, g_xdblp);
    cudaGetSymbolAddress((void**)&xdbl,  g_xdbl);
    cudaGetSymbolAddress((void**)&delta, g_delta);
    cudaGetSymbolAddress((void**)&ys,    g_ys);
    cudaGetSymbolAddress((void**)&outp,  g_outp);
    cudaGetSymbolAddress((void**)&sA,    g_sA);
    cudaGetSymbolAddress((void**)&sS,    g_sS);
    cudaGetSymbolAddress((void**)&hc,    g_hc);

    __nv_bfloat16 *xh, *xl, *wih, *wil, *uh, *ul, *wxh, *wxl;
    __nv_bfloat16 *xdh, *xdl, *wdh, *wdl, *ygh, *ygl, *woh, *wol;
    cudaGetSymbolAddress((void**)&xh,  g_xh);  cudaGetSymbolAddress((void**)&xl,  g_xl);
    cudaGetSymbolAddress((void**)&wih, g_wih); cudaGetSymbolAddress((void**)&wil, g_wil);
    cudaGetSymbolAddress((void**)&uh,  g_uh);  cudaGetSymbolAddress((void**)&ul,  g_ul);
    cudaGetSymbolAddress((void**)&wxh, g_wxh); cudaGetSymbolAddress((void**)&wxl, g_wxl);
    cudaGetSymbolAddress((void**)&xdh, g_xdh); cudaGetSymbolAddress((void**)&xdl, g_xdl);
    cudaGetSymbolAddress((void**)&wdh, g_wdh); cudaGetSymbolAddress((void**)&wdl, g_wdl);
    cudaGetSymbolAddress((void**)&ygh, g_ygh); cudaGetSymbolAddress((void**)&ygl, g_ygl);
    cudaGetSymbolAddress((void**)&woh, g_woh); cudaGetSymbolAddress((void**)&wol, g_wol);

    cudaFuncSetAttribute(gemm_mma<0>, cudaFuncAttributeMaxDynamicSharedMemorySize, GEMM_SMEM);
    cudaFuncSetAttribute(gemm_mma<1>, cudaFuncAttributeMaxDynamicSharedMemorySize, GEMM_SMEM);
    cudaFuncSetAttribute(gemm_mma<2>, cudaFuncAttributeMaxDynamicSharedMemorySize, GEMM_SMEM);

    const int EW2 = NTOK * DINNER / 2;
#define CVT(src, hi, lo, n) \
    cvt_split<<<(n) / 1024, 256>>>((const float4*)(src), (__nv_bfloat162*)(hi), \
                                   (__nv_bfloat162*)(lo), (n) / 4)

    // launches 0-2: conversions — keeps in_proj gemm at profiled index 3
    CVT(x, xh, xl, NTOK * DMODEL);
    CVT(d_in[1], wih, wil, 4096 * DMODEL);
    CVT(d_in[4], wxh, wxl, XDBL * DINNER);
    // launch 3 (PROFILED): in_proj xr = x @ in_w^T  (4096 x 4096 x 1024)
    gemm_mma<0><<<dim3(32, 32), 256, GEMM_SMEM>>>(
        xh, xl, wih, wil, xr, nullptr, 4096, DMODEL, DMODEL, DMODEL, 4096, 0);
    // conv + silu -> u, uh, ul
    conv_silu_kernel<<<EW2 / 256, 256>>>(xr, conv_w, conv_b, u,
                                         (__nv_bfloat162*)uh, (__nv_bfloat162*)ul);
    // x_proj splitK(4) slabs (4096 x 96 x 2048), grid (1,32,NSLAB)
    gemm_mma<2><<<dim3(1, 32, NSLAB), 256, GEMM_SMEM>>>(
        uh, ul, wxh, wxl, xdblp, nullptr, XDBL, DINNER / NSLAB,
        DINNER, DINNER, XDBL, NTOK * XDBL);
    reduce_split_kernel<<<(NTOK * XDBL / 4 + 255) / 256, 256>>>(
        (const float4*)xdblp, (float4*)xdbl,
        (__nv_bfloat162*)xdh, (__nv_bfloat162*)xdl, NTOK * XDBL / 4);
    // dt_proj + bias + softplus: delta (4096 x 2048 x 64)
    CVT(d_in[5], wdh, wdl, DINNER * DTRANK);
    gemm_mma<1><<<dim3(16, 32), 256, GEMM_SMEM>>>(
        xdh, xdl, wdh, wdl, delta, dtproj_b, DINNER, DTRANK, XDBL, DTRANK, DINNER, 0);
    // chunked parallel scan
    scan_pass1<<<NSCAN / 256, 256>>>(delta, u, xdbl, A_log, sA, sS);
    scan_pass2<<<(NTOK * DSTATE) / 256, 256>>>(sA, sS, hc);
    scan_pass3<<<NSCAN / 256, 256>>>(delta, u, xdbl, A_log, hc, ys);
    // gate -> ygh/ygl
    gate_kernel<<<EW2 / 256, 256>>>(ys, u, Dvec, xr,
                                    (__nv_bfloat162*)ygh, (__nv_bfloat162*)ygl);
    // out_proj splitK(4) slabs: (4096 x 1024 x 2048), grid (8,32,OSLAB)
    CVT(d_in[9], woh, wol, DMODEL * DINNER);
    gemm_mma<2><<<dim3(8, 32, OSLAB), 256, GEMM_SMEM>>>(
        ygh, ygl, woh, wol, outp, nullptr, DMODEL, DINNER / OSLAB,
        DINNER, DINNER, DMODEL, NTOK * DMODEL);
    reduce_out_kernel<<<(NTOK * DMODEL / 4 + 255) / 256, 256>>>(
        (const float4*)outp, (float4*)out, NTOK * DMODEL / 4);
#undef CVT
}

// round 15
// speedup vs baseline: 1.2538x; 1.2099x over previous
#include <cuda_runtime.h>
#include <cuda_bf16.h>
#include <cstdint>

// ---------------------------------------------------------------------------
// Mamba block forward. R15: R14 exactly (838us verified) with scan passes
// restructured to one-thread-per-channel-chunk (16 states in registers,
// float4 B/C loads, no shuffle). R14 scan was LSU-issue-bound (~29M warp-LDG
// ~= 205us); new form issues ~4.6M -> MUFU-bound ~80us.
// B=2, L=2048, D_MODEL=1024, D_INNER=2048, D_STATE=16, DT_RANK=64, D_CONV=4
// ---------------------------------------------------------------------------

#define NTOK   4096
#define DMODEL 1024
#define DINNER 2048
#define DSTATE 16
#define DTRANK 64
#define XDBL   96
#define LSEQ   2048
#define NSLAB  4
#define OSLAB  4
#define NCH    16
#define CLEN   (LSEQ / NCH)            // 128
#define NCHAN  (NTOK / LSEQ * 2048 * 2)  // placeholder not used
#define NSCAN  (NTOK * DSTATE * NCH)   // 1048576

// fp32 scratch
__device__ float g_xr[(size_t)NTOK * 4096];
__device__ float g_u[(size_t)NTOK * DINNER];
__device__ float g_xdblp[(size_t)NSLAB * NTOK * XDBL];
__device__ float g_xdbl[(size_t)NTOK * XDBL];
__device__ float g_delta[(size_t)NTOK * DINNER];
__device__ float g_ys[(size_t)NTOK * DINNER];
__device__ float g_outp[(size_t)OSLAB * NTOK * DMODEL];
__device__ float g_sA[NSCAN], g_sS[NSCAN], g_hc[NSCAN];

// bf16 hi/lo scratch
__device__ __nv_bfloat16 g_xh[(size_t)NTOK * DMODEL],  g_xl[(size_t)NTOK * DMODEL];
__device__ __nv_bfloat16 g_wih[(size_t)4096 * DMODEL], g_wil[(size_t)4096 * DMODEL];
__device__ __nv_bfloat16 g_uh[(size_t)NTOK * DINNER],  g_ul[(size_t)NTOK * DINNER];
__device__ __nv_bfloat16 g_wxh[(size_t)XDBL * DINNER], g_wxl[(size_t)XDBL * DINNER];
__device__ __nv_bfloat16 g_xdh[(size_t)NTOK * XDBL],   g_xdl[(size_t)NTOK * XDBL];
__device__ __nv_bfloat16 g_wdh[(size_t)DINNER * DTRANK], g_wdl[(size_t)DINNER * DTRANK];
__device__ __nv_bfloat16 g_ygh[(size_t)NTOK * DINNER], g_ygl[(size_t)NTOK * DINNER];
__device__ __nv_bfloat16 g_woh[(size_t)DMODEL * DINNER], g_wol[(size_t)DMODEL * DINNER];

__device__ __forceinline__ uint32_t smem_to_u32(const void* p) {
    uint32_t a;
    asm("{ .reg .u64 t; cvta.to.shared.u64 t, %1; cvt.u32.u64 %0, t; }"
        : "=r"(a) : "l"(p));
    return a;
}

#define CP_ASYNC16(dst, src) \
    asm volatile("cp.async.cg.shared.global [%0], [%1], 16;" :: "r"(dst), "l"(src))
#define CP_COMMIT() asm volatile("cp.async.commit_group;" ::: "memory")
#define CP_WAIT0()  asm volatile("cp.async.wait_group 0;" ::: "memory")
#define CP_WAIT1()  asm volatile("cp.async.wait_group 1;" ::: "memory")

#define LDSM_X4(r0, r1, r2, r3, a) \
    asm volatile("ldmatrix.sync.aligned.m8n8.x4.shared.b16 {%0,%1,%2,%3}, [%4];" \
        : "=r"(r0), "=r"(r1), "=r"(r2), "=r"(r3) : "r"(a))

#define MMA_BF16(d, a, b) \
    asm volatile("mma.sync.aligned.m16n8k16.row.col.f32.bf16.bf16.f32 " \
        "{%0,%1,%2,%3}, {%4,%5,%6,%7}, {%8,%9}, {%0,%1,%2,%3};" \
        : "+f"((d)[0]), "+f"((d)[1]), "+f"((d)[2]), "+f"((d)[3]) \
        : "r"((a)[0]), "r"((a)[1]), "r"((a)[2]), "r"((a)[3]), \
          "r"((b)[0]), "r"((b)[1]))

__device__ __forceinline__ uint32_t swoff(int row, int c) {
    return (uint32_t)(row * 64 + ((c ^ ((row >> 1) & 3)) << 4));
}

__device__ __forceinline__ float softplus_f(float v) {
    if (v > 20.f)  return v;
    if (v < -20.f) return __expf(v);
    return log1pf(__expf(v));
}

// ===========================================================================
// 128x128 NT GEMM, bf16 hi/lo split, 2-stage cp.async, 2 CTAs/SM (R12 exact).
// EPI: 0 = store, 1 = softplus(v+bias[col]) store,
//      2 = splitK slab: blockIdx.z = k-slice, store to C + z*sstride.
// ===========================================================================
#define GSTAGE 32768
#define GEMM_SMEM (2 * GSTAGE)

template <int EPI>
__global__ __launch_bounds__(256, 2) void gemm_mma(
    const __nv_bfloat16* __restrict__ Ah, const __nv_bfloat16* __restrict__ Al,
    const __nv_bfloat16* __restrict__ Bh, const __nv_bfloat16* __restrict__ Bl,
    float* __restrict__ C, const float* __restrict__ bias,
    int N, int Kc, int lda, int ldb, int ldc, int sstride)
{
    extern __shared__ char smem[];
    const uint32_t sb = smem_to_u32(smem);
    const int tid  = threadIdx.x;
    const int wid  = tid >> 5;
    const int lane = tid & 31;
    const int wm = wid & 1;
    const int wn = wid >> 1;
    const int row0 = blockIdx.y * 128;
    const int col0 = blockIdx.x * 128;
    const int kstart = (EPI == 2) ? blockIdx.z * Kc : 0;
    if (EPI == 2) C += (size_t)blockIdx.z * sstride;

    const int lr = tid >> 2;
    const int lc = tid & 3;

    const int a_rl = lane & 15;
    const int a_kc = lane >> 4;
    const int b_rl = (lane & 7) + ((lane >> 4) << 3);
    const int b_kc = (lane >> 3) & 1;

    float acc[4][4][4];
#pragma unroll
    for (int i = 0; i < 4; ++i)
#pragma unroll
        for (int j = 0; j < 4; ++j)
#pragma unroll
            for (int q = 0; q < 4; ++q) acc[i][j][q] = 0.f;

    const int nch = Kc >> 5;

    auto load_stage = [&](int stage, int k0) {
#pragma unroll
        for (int i = 0; i < 8; ++i) {
            const int tile = i >> 1;
            const int r = ((i & 1) << 6) + lr;
            const uint32_t dst = sb + stage * GSTAGE + tile * 8192 + swoff(r, lc);
            const __nv_bfloat16* src;
            if (tile < 2) {
                const __nv_bfloat16* base = tile ? Al : Ah;
                src = base + (size_t)(row0 + r) * lda + k0 + lc * 8;
            } else {
                int gn = col0 + r; if (gn >= N) gn = N - 1;
                const __nv_bfloat16* base = (tile == 2) ? Bh : Bl;
                src = base + (size_t)gn * ldb + k0 + lc * 8;
            }
            CP_ASYNC16(dst, src);
        }
    };

    load_stage(0, kstart);
    CP_COMMIT();

    for (int ch = 0; ch < nch; ++ch) {
        if (ch + 1 < nch) {
            load_stage((ch + 1) & 1, kstart + ((ch + 1) << 5));
            CP_COMMIT();
            CP_WAIT1();
        } else {
            CP_WAIT0();
        }
        __syncthreads();

        const uint32_t st = sb + (ch & 1) * GSTAGE;
#pragma unroll
        for (int ks = 0; ks < 2; ++ks) {
            uint32_t ah[4][4], al[4][4];
#pragma unroll
            for (int mt = 0; mt < 4; ++mt) {
                const int row = wm * 64 + mt * 16 + a_rl;
                const uint32_t ad = st + swoff(row, ks * 2 + a_kc);
                LDSM_X4(ah[mt][0], ah[mt][1], ah[mt][2], ah[mt][3], ad);
                LDSM_X4(al[mt][0], al[mt][1], al[mt][2], al[mt][3], ad + 8192);
            }
            uint32_t bh[2][4], bl[2][4];
#pragma unroll
            for (int p = 0; p < 2; ++p) {
                const int row = wn * 32 + p * 16 + b_rl;
                const uint32_t bd = st + 16384 + swoff(row, ks * 2 + b_kc);
                LDSM_X4(bh[p][0], bh[p][1], bh[p][2], bh[p][3], bd);
                LDSM_X4(bl[p][0], bl[p][1], bl[p][2], bl[p][3], bd + 8192);
            }
#pragma unroll
            for (int mt = 0; mt < 4; ++mt)
#pragma unroll
                for (int nt = 0; nt < 4; ++nt) {
                    uint32_t bfh[2] = { bh[nt >> 1][(nt & 1) * 2],
                                        bh[nt >> 1][(nt & 1) * 2 + 1] };
                    uint32_t bfl[2] = { bl[nt >> 1][(nt & 1) * 2],
                                        bl[nt >> 1][(nt & 1) * 2 + 1] };
                    MMA_BF16(acc[mt][nt], ah[mt], bfh);
                    MMA_BF16(acc[mt][nt], ah[mt], bfl);
                    MMA_BF16(acc[mt][nt], al[mt], bfh);
                }
        }
        __syncthreads();
    }

#pragma unroll
    for (int mt = 0; mt < 4; ++mt) {
        const int r = row0 + wm * 64 + mt * 16 + (lane >> 2);
#pragma unroll
        for (int nt = 0; nt < 4; ++nt) {
            const int cb = col0 + wn * 32 + nt * 8 + ((lane & 3) << 1);
            if (cb >= N) continue;
            if (EPI == 1) {
                const float b0 = bias[cb], b1 = bias[cb + 1];
                *(float2*)(C + (size_t)r * ldc + cb) = make_float2(
                    softplus_f(acc[mt][nt][0] + b0), softplus_f(acc[mt][nt][1] + b1));
                *(float2*)(C + (size_t)(r + 8) * ldc + cb) = make_float2(
                    softplus_f(acc[mt][nt][2] + b0), softplus_f(acc[mt][nt][3] + b1));
            } else {
                *(float2*)(C + (size_t)r * ldc + cb) =
                    make_float2(acc[mt][nt][0], acc[mt][nt][1]);
                *(float2*)(C + (size_t)(r + 8) * ldc + cb) =
                    make_float2(acc[mt][nt][2], acc[mt][nt][3]);
            }
        }
    }
}

// ---------------------------------------------------------------------------
__global__ __launch_bounds__(256) void cvt_split(
    const float4* __restrict__ src, __nv_bfloat162* __restrict__ hi,
    __nv_bfloat162* __restrict__ lo, int n4)
{
    int i = blockIdx.x * blockDim.x + threadIdx.x;
    if (i >= n4) return;
    float4 v = src[i];
    __nv_bfloat16 h0 = __float2bfloat16(v.x), h1 = __float2bfloat16(v.y);
    __nv_bfloat16 h2 = __float2bfloat16(v.z), h3 = __float2bfloat16(v.w);
    hi[2 * i]     = __halves2bfloat162(h0, h1);
    hi[2 * i + 1] = __halves2bfloat162(h2, h3);
    lo[2 * i]     = __halves2bfloat162(
        __float2bfloat16(v.x - __bfloat162float(h0)),
        __float2bfloat16(v.y - __bfloat162float(h1)));
    lo[2 * i + 1] = __halves2bfloat162(
        __float2bfloat16(v.z - __bfloat162float(h2)),
        __float2bfloat16(v.w - __bfloat162float(h3)));
}

// sum NSLAB splitK slabs -> fp32 xdbl + bf16 hi/lo
__global__ __launch_bounds__(256) void reduce_split_kernel(
    const float4* __restrict__ slabs, float4* __restrict__ xdbl,
    __nv_bfloat162* __restrict__ hi, __nv_bfloat162* __restrict__ lo, int n4)
{
    int i = blockIdx.x * blockDim.x + threadIdx.x;
    if (i >= n4) return;
    float4 v = slabs[i];
#pragma unroll
    for (int s = 1; s < NSLAB; ++s) {
        float4 w = slabs[(size_t)s * n4 + i];
        v.x += w.x; v.y += w.y; v.z += w.z; v.w += w.w;
    }
    xdbl[i] = v;
    __nv_bfloat16 h0 = __float2bfloat16(v.x), h1 = __float2bfloat16(v.y);
    __nv_bfloat16 h2 = __float2bfloat16(v.z), h3 = __float2bfloat16(v.w);
    hi[2 * i]     = __halves2bfloat162(h0, h1);
    hi[2 * i + 1] = __halves2bfloat162(h2, h3);
    lo[2 * i]     = __halves2bfloat162(
        __float2bfloat16(v.x - __bfloat162float(h0)),
        __float2bfloat16(v.y - __bfloat162float(h1)));
    lo[2 * i + 1] = __halves2bfloat162(
        __float2bfloat16(v.z - __bfloat162float(h2)),
        __float2bfloat16(v.w - __bfloat162float(h3)));
}

// sum OSLAB out_proj slabs -> final fp32 out
__global__ __launch_bounds__(256) void reduce_out_kernel(
    const float4* __restrict__ slabs, float4* __restrict__ out, int n4)
{
    int i = blockIdx.x * blockDim.x + threadIdx.x;
    if (i >= n4) return;
    float4 v = slabs[i];
#pragma unroll
    for (int s = 1; s < OSLAB; ++s) {
        float4 w = slabs[(size_t)s * n4 + i];
        v.x += w.x; v.y += w.y; v.z += w.z; v.w += w.w;
    }
    out[i] = v;
}

// causal dwconv(4) + bias + SiLU, 2 channels/thread (float2) — ncu-verified.
__global__ __launch_bounds__(256) void conv_silu_kernel(
    const float* __restrict__ xr, const float* __restrict__ cw,
    const float* __restrict__ cb, float* __restrict__ u,
    __nv_bfloat162* __restrict__ uh, __nv_bfloat162* __restrict__ ul)
{
    int idx = blockIdx.x * blockDim.x + threadIdx.x;
    if (idx >= NTOK * DINNER / 2) return;
    int dp = idx & (DINNER / 2 - 1);
    int d  = dp << 1;
    int m  = idx >> 10;
    int b  = m >> 11;
    int l  = m & (LSEQ - 1);

    float4 w0 = *(const float4*)(cw + d * 4);
    float4 w1 = *(const float4*)(cw + d * 4 + 4);
    float2 a = make_float2(cb[d], cb[d + 1]);
    int base = b << 11;
    const float* p = xr + (size_t)(base + l) * 4096 + d;
    float2 t;
    if (l >= 3) { t = *(const float2*)(p - 3 * 4096);
                  a.x = fmaf(t.x, w0.x, a.x); a.y = fmaf(t.y, w1.x, a.y); }
    if (l >= 2) { t = *(const float2*)(p - 2 * 4096);
                  a.x = fmaf(t.x, w0.y, a.x); a.y = fmaf(t.y, w1.y, a.y); }
    if (l >= 1) { t = *(const float2*)(p - 1 * 4096);
                  a.x = fmaf(t.x, w0.z, a.x); a.y = fmaf(t.y, w1.z, a.y); }
    t = *(const float2*)p;
    a.x = fmaf(t.x, w0.w, a.x); a.y = fmaf(t.y, w1.w, a.y);

    float vx = a.x / (1.f + __expf(-a.x));
    float vy = a.y / (1.f + __expf(-a.y));
    *(float2*)(u + (size_t)idx * 2) = make_float2(vx, vy);
    __nv_bfloat16 hx = __float2bfloat16(vx), hy = __float2bfloat16(vy);
    uh[idx] = __halves2bfloat162(hx, hy);
    ul[idx] = __halves2bfloat162(
        __float2bfloat16(vx - __bfloat162float(hx)),
        __float2bfloat16(vy - __bfloat162float(hy)));
}

// ---------------------------------------------------------------------------
// Chunked parallel scan, one thread per (channel, chunk): 16 states in regs.
// pass1: local (a[16], s[16]); pass2: serial carry combine per (ch,n);
// pass3: replay with carry, emit y = sum_n h[n]*C[n].
// sA/sS/hc layout: idx = (c<<16) | (ch<<4) | n  (n contiguous -> float4).
// ---------------------------------------------------------------------------
__global__ __launch_bounds__(256) void scan_pass1(
    const float* __restrict__ delta, const float* __restrict__ u,
    const float* __restrict__ xdbl, const float* __restrict__ A_log,
    float* __restrict__ sA, float* __restrict__ sS)
{
    int gid = blockIdx.x * blockDim.x + threadIdx.x;   // 0..65535
    int ch = gid & 4095;
    int c  = gid >> 12;
    int b = ch >> 11, d = ch & (DINNER - 1);

    float A[DSTATE];
#pragma unroll
    for (int q = 0; q < 4; ++q) {
        float4 al4 = *(const float4*)(A_log + d * DSTATE + q * 4);
        A[q * 4 + 0] = -__expf(al4.x); A[q * 4 + 1] = -__expf(al4.y);
        A[q * 4 + 2] = -__expf(al4.z); A[q * 4 + 3] = -__expf(al4.w);
    }

    const size_t chanBase = (size_t)(b << 11) * DINNER + d;
    const float* dp = delta + chanBase;
    const float* up = u + chanBase;
    const float* xd = xdbl + (size_t)(b << 11) * XDBL;

    float a[DSTATE], h[DSTATE];
#pragma unroll
    for (int n = 0; n < DSTATE; ++n) { a[n] = 1.f; h[n] = 0.f; }

    const int l0 = c * CLEN;
    for (int i = 0; i < CLEN; ++i) {
        const int l = l0 + i;
        float dl = dp[(size_t)l * DINNER];
        float ul = up[(size_t)l * DINNER];
        const float* bp = xd + l * XDBL + DTRANK;
        float B[DSTATE];
#pragma unroll
        for (int q = 0; q < 4; ++q)
            *(float4*)(B + q * 4) = *(const float4*)(bp + q * 4);
        float du = dl * ul;
#pragma unroll
        for (int n = 0; n < DSTATE; ++n) {
            float dA = __expf(dl * A[n]);
            h[n] = fmaf(dA, h[n], du * B[n]);
            a[n] *= dA;
        }
    }
    const int base = (c << 16) | (ch << 4);
#pragma unroll
    for (int q = 0; q < 4; ++q) {
        *(float4*)(sA + base + q * 4) = *(const float4*)(a + q * 4);
        *(float4*)(sS + base + q * 4) = *(const float4*)(h + q * 4);
    }
}

__global__ __launch_bounds__(256) void scan_pass2(
    const float* __restrict__ sA, const float* __restrict__ sS,
    float* __restrict__ hcar)
{
    int gid = blockIdx.x * blockDim.x + threadIdx.x;   // 0..65535 = (ch<<4)|n
    float hc = 0.f;
#pragma unroll
    for (int c = 0; c < NCH; ++c) {
        int idx = (c << 16) | gid;
        hcar[idx] = hc;
        hc = fmaf(sA[idx], hc, sS[idx]);
    }
}

__global__ __launch_bounds__(256) void scan_pass3(
    const float* __restrict__ delta, const float* __restrict__ u,
    const float* __restrict__ xdbl, const float* __restrict__ A_log,
    const float* __restrict__ hcar, float* __restrict__ ys)
{
    int gid = blockIdx.x * blockDim.x + threadIdx.x;   // 0..65535
    int ch = gid & 4095;
    int c  = gid >> 12;
    int b = ch >> 11, d = ch & (DINNER - 1);

    float A[DSTATE];
#pragma unroll
    for (int q = 0; q < 4; ++q) {
        float4 al4 = *(const float4*)(A_log + d * DSTATE + q * 4);
        A[q * 4 + 0] = -__expf(al4.x); A[q * 4 + 1] = -__expf(al4.y);
        A[q * 4 + 2] = -__expf(al4.z); A[q * 4 + 3] = -__expf(al4.w);
    }

    const size_t chanBase = (size_t)(b << 11) * DINNER + d;
    const float* dp = delta + chanBase;
    const float* up = u + chanBase;
    const float* xd = xdbl + (size_t)(b << 11) * XDBL;
    float* yp = ys + chanBase;

    float h[DSTATE];
    const int base = (c << 16) | (ch << 4);
#pragma unroll
    for (int q = 0; q < 4; ++q)
        *(float4*)(h + q * 4) = *(const float4*)(hcar + base + q * 4);

    const int l0 = c * CLEN;
    for (int i = 0; i < CLEN; ++i) {
        const int l = l0 + i;
        float dl = dp[(size_t)l * DINNER];
        float ul = up[(size_t)l * DINNER];
        const float* bp = xd + l * XDBL + DTRANK;
        float B[DSTATE], Cc[DSTATE];
#pragma unroll
        for (int q = 0; q < 4; ++q) {
            *(float4*)(B + q * 4)  = *(const float4*)(bp + q * 4);
            *(float4*)(Cc + q * 4) = *(const float4*)(bp + DSTATE + q * 4);
        }
        float du = dl * ul;
        float v = 0.f;
#pragma unroll
        for (int n = 0; n < DSTATE; ++n) {
            float dA = __expf(dl * A[n]);
            h[n] = fmaf(dA, h[n], du * B[n]);
            v = fmaf(h[n], Cc[n], v);
        }
        yp[(size_t)l * DINNER] = v;
    }
}

// y = (ys + u*D) * silu(res), 2 channels/thread; emits bf16 hi/lo.
__global__ __launch_bounds__(256) void gate_kernel(
    const float* __restrict__ ys, const float* __restrict__ u,
    const float* __restrict__ Dp, const float* __restrict__ xr,
    __nv_bfloat162* __restrict__ ygh, __nv_bfloat162* __restrict__ ygl)
{
    int idx = blockIdx.x * blockDim.x + threadIdx.x;
    if (idx >= NTOK * DINNER / 2) return;
    int dpair = idx & (DINNER / 2 - 1);
    int d = dpair << 1;
    int m = idx >> 10;
    float2 res = *(const float2*)(xr + (size_t)m * 4096 + DINNER + d);
    float2 yv  = *(const float2*)(ys + (size_t)idx * 2);
    float2 uv  = *(const float2*)(u + (size_t)idx * 2);
    float2 Dv  = *(const float2*)(Dp + d);
    float gx = res.x / (1.f + __expf(-res.x));
    float gy = res.y / (1.f + __expf(-res.y));
    float vx = (yv.x + uv.x * Dv.x) * gx;
    float vy = (yv.y + uv.y * Dv.y) * gy;
    __nv_bfloat16 hx = __float2bfloat16(vx), hy = __float2bfloat16(vy);
    ygh[idx] = __halves2bfloat162(hx, hy);
    ygl[idx] = __halves2bfloat162(
        __float2bfloat16(vx - __bfloat162float(hx)),
        __float2bfloat16(vy - __bfloat162float(hy)));
}

// ---------------------------------------------------------------------------
extern "C" void kernel_launch(void* const* d_in, const int* in_sizes, int n_in,
                              void* d_out, int out_size)
{
    const float* x        = (const float*)d_in[0];
    const float* conv_w   = (const float*)d_in[2];
    const float* conv_b   = (const float*)d_in[3];
    const float* dtproj_b = (const float*)d_in[6];
    const float* A_log    = (const float*)d_in[7];
    const float* Dvec     = (const float*)d_in[8];
    float* out            = (float*)d_out;

    float *xr, *u, *xdblp, *xdbl, *delta, *ys, *outp, *sA, *sS, *hc;
    cudaGetSymbolAddress((void**)&xr,    g_xr);
    cudaGetSymbolAddress((void**)&u,     g_u);
    cudaGetSymbolAddress((void**)&xdblp, g_xdblp);
    cudaGetSymbolAddress((void**)&xdbl,  g_xdbl);
    cudaGetSymbolAddress((void**)&delta, g_delta);
    cudaGetSymbolAddress((void**)&ys,    g_ys);
    cudaGetSymbolAddress((void**)&outp,  g_outp);
    cudaGetSymbolAddress((void**)&sA,    g_sA);
    cudaGetSymbolAddress((void**)&sS,    g_sS);
    cudaGetSymbolAddress((void**)&hc,    g_hc);

    __nv_bfloat16 *xh, *xl, *wih, *wil, *uh, *ul, *wxh, *wxl;
    __nv_bfloat16 *xdh, *xdl, *wdh, *wdl, *ygh, *ygl, *woh, *wol;
    cudaGetSymbolAddress((void**)&xh,  g_xh);  cudaGetSymbolAddress((void**)&xl,  g_xl);
    cudaGetSymbolAddress((void**)&wih, g_wih); cudaGetSymbolAddress((void**)&wil, g_wil);
    cudaGetSymbolAddress((void**)&uh,  g_uh);  cudaGetSymbolAddress((void**)&ul,  g_ul);
    cudaGetSymbolAddress((void**)&wxh, g_wxh); cudaGetSymbolAddress((void**)&wxl, g_wxl);
    cudaGetSymbolAddress((void**)&xdh, g_xdh); cudaGetSymbolAddress((void**)&xdl, g_xdl);
    cudaGetSymbolAddress((void**)&wdh, g_wdh); cudaGetSymbolAddress((void**)&wdl, g_wdl);
    cudaGetSymbolAddress((void**)&ygh, g_ygh); cudaGetSymbolAddress((void**)&ygl, g_ygl);
    cudaGetSymbolAddress((void**)&woh, g_woh); cudaGetSymbolAddress((void**)&wol, g_wol);

    cudaFuncSetAttribute(gemm_mma<0>, cudaFuncAttributeMaxDynamicSharedMemorySize, GEMM_SMEM);
    cudaFuncSetAttribute(gemm_mma<1>, cudaFuncAttributeMaxDynamicSharedMemorySize, GEMM_SMEM);
    cudaFuncSetAttribute(gemm_mma<2>, cudaFuncAttributeMaxDynamicSharedMemorySize, GEMM_SMEM);

    const int EW2 = NTOK * DINNER / 2;
#define CVT(src, hi, lo, n) \
    cvt_split<<<(n) / 1024, 256>>>((const float4*)(src), (__nv_bfloat162*)(hi), \
                                   (__nv_bfloat162*)(lo), (n) / 4)

    // launches 0-2: conversions — keeps in_proj gemm at profiled index 3
    CVT(x, xh, xl, NTOK * DMODEL);
    CVT(d_in[1], wih, wil, 4096 * DMODEL);
    CVT(d_in[4], wxh, wxl, XDBL * DINNER);
    // launch 3 (PROFILED): in_proj xr = x @ in_w^T  (4096 x 4096 x 1024)
    gemm_mma<0><<<dim3(32, 32), 256, GEMM_SMEM>>>(
        xh, xl, wih, wil, xr, nullptr, 4096, DMODEL, DMODEL, DMODEL, 4096, 0);
    // conv + silu -> u, uh, ul
    conv_silu_kernel<<<EW2 / 256, 256>>>(xr, conv_w, conv_b, u,
                                         (__nv_bfloat162*)uh, (__nv_bfloat162*)ul);
    // x_proj splitK(4) slabs (4096 x 96 x 2048), grid (1,32,NSLAB)
    gemm_mma<2><<<dim3(1, 32, NSLAB), 256, GEMM_SMEM>>>(
        uh, ul, wxh, wxl, xdblp, nullptr, XDBL, DINNER / NSLAB,
        DINNER, DINNER, XDBL, NTOK * XDBL);
    reduce_split_kernel<<<(NTOK * XDBL / 4 + 255) / 256, 256>>>(
        (const float4*)xdblp, (float4*)xdbl,
        (__nv_bfloat162*)xdh, (__nv_bfloat162*)xdl, NTOK * XDBL / 4);
    // dt_proj + bias + softplus: delta (4096 x 2048 x 64)
    CVT(d_in[5], wdh, wdl, DINNER * DTRANK);
    gemm_mma<1><<<dim3(16, 32), 256, GEMM_SMEM>>>(
        xdh, xdl, wdh, wdl, delta, dtproj_b, DINNER, DTRANK, XDBL, DTRANK, DINNER, 0);
    // chunked parallel scan (thread-per-channel-chunk, 16 states in regs)
    scan_pass1<<<(NTOK / LSEQ * 2048 * NCH * 2) / 256 / 2, 256>>>(delta, u, xdbl, A_log, sA, sS);
    // note: grid = 4096*16/256 = 256 blocks
    scan_pass2<<<(NTOK * DSTATE) / 256, 256>>>(sA, sS, hc);
    scan_pass3<<<(4096 * NCH) / 256, 256>>>(delta, u, xdbl, A_log, hc, ys);
    // gate -> ygh/ygl
    gate_kernel<<<EW2 / 256, 256>>>(ys, u, Dvec, xr,
                                    (__nv_bfloat162*)ygh, (__nv_bfloat162*)ygl);
    // out_proj splitK(4) slabs: (4096 x 1024 x 2048), grid (8,32,OSLAB)
    CVT(d_in[9], woh, wol, DMODEL * DINNER);
    gemm_mma<2><<<dim3(8, 32, OSLAB), 256, GEMM_SMEM>>>(
        ygh, ygl, woh, wol, outp, nullptr, DMODEL, DINNER / OSLAB,
        DINNER, DINNER, DMODEL, NTOK * DMODEL);
    reduce_out_kernel<<<(NTOK * DMODEL / 4 + 255) / 256, 256>>>(
        (const float4*)outp, (float4*)out, NTOK * DMODEL / 4);
#undef CVT
}

// round 17
// speedup vs baseline: 1.2691x; 1.0122x over previous
#include <cuda_runtime.h>
#include <cuda_bf16.h>
#include <cstdint>

// ---------------------------------------------------------------------------
// Mamba block forward. R16: (a) out_proj back to direct GEMM (256 CTAs = one
// wave at 2 CTAs/SM; kills reduce_out + 256MB slab traffic), (b) GEMM
// mainloop 3-stage single-sync (cutlass ordering) to halve barrier count —
// R12/13 showed idle tensor time is barrier exposure, not load latency.
// B=2, L=2048, D_MODEL=1024, D_INNER=2048, D_STATE=16, DT_RANK=64, D_CONV=4
// ---------------------------------------------------------------------------

#define NTOK   4096
#define DMODEL 1024
#define DINNER 2048
#define DSTATE 16
#define DTRANK 64
#define XDBL   96
#define LSEQ   2048
#define NSLAB  4
#define NCH    16
#define CLEN   (LSEQ / NCH)            // 128
#define NSCAN  (NTOK * DSTATE * NCH)

// fp32 scratch
__device__ float g_xr[(size_t)NTOK * 4096];
__device__ float g_u[(size_t)NTOK * DINNER];
__device__ float g_xdblp[(size_t)NSLAB * NTOK * XDBL];
__device__ float g_xdbl[(size_t)NTOK * XDBL];
__device__ float g_delta[(size_t)NTOK * DINNER];
__device__ float g_ys[(size_t)NTOK * DINNER];
__device__ float g_sA[NSCAN], g_sS[NSCAN], g_hc[NSCAN];

// bf16 hi/lo scratch
__device__ __nv_bfloat16 g_xh[(size_t)NTOK * DMODEL],  g_xl[(size_t)NTOK * DMODEL];
__device__ __nv_bfloat16 g_wih[(size_t)4096 * DMODEL], g_wil[(size_t)4096 * DMODEL];
__device__ __nv_bfloat16 g_uh[(size_t)NTOK * DINNER],  g_ul[(size_t)NTOK * DINNER];
__device__ __nv_bfloat16 g_wxh[(size_t)XDBL * DINNER], g_wxl[(size_t)XDBL * DINNER];
__device__ __nv_bfloat16 g_xdh[(size_t)NTOK * XDBL],   g_xdl[(size_t)NTOK * XDBL];
__device__ __nv_bfloat16 g_wdh[(size_t)DINNER * DTRANK], g_wdl[(size_t)DINNER * DTRANK];
__device__ __nv_bfloat16 g_ygh[(size_t)NTOK * DINNER], g_ygl[(size_t)NTOK * DINNER];
__device__ __nv_bfloat16 g_woh[(size_t)DMODEL * DINNER], g_wol[(size_t)DMODEL * DINNER];

__device__ __forceinline__ uint32_t smem_to_u32(const void* p) {
    uint32_t a;
    asm("{ .reg .u64 t; cvta.to.shared.u64 t, %1; cvt.u32.u64 %0, t; }"
        : "=r"(a) : "l"(p));
    return a;
}

#define CP_ASYNC16(dst, src) \
    asm volatile("cp.async.cg.shared.global [%0], [%1], 16;" :: "r"(dst), "l"(src))
#define CP_COMMIT() asm volatile("cp.async.commit_group;" ::: "memory")
#define CP_WAIT0()  asm volatile("cp.async.wait_group 0;" ::: "memory")
#define CP_WAIT1()  asm volatile("cp.async.wait_group 1;" ::: "memory")

#define LDSM_X4(r0, r1, r2, r3, a) \
    asm volatile("ldmatrix.sync.aligned.m8n8.x4.shared.b16 {%0,%1,%2,%3}, [%4];" \
        : "=r"(r0), "=r"(r1), "=r"(r2), "=r"(r3) : "r"(a))

#define MMA_BF16(d, a, b) \
    asm volatile("mma.sync.aligned.m16n8k16.row.col.f32.bf16.bf16.f32 " \
        "{%0,%1,%2,%3}, {%4,%5,%6,%7}, {%8,%9}, {%0,%1,%2,%3};" \
        : "+f"((d)[0]), "+f"((d)[1]), "+f"((d)[2]), "+f"((d)[3]) \
        : "r"((a)[0]), "r"((a)[1]), "r"((a)[2]), "r"((a)[3]), \
          "r"((b)[0]), "r"((b)[1]))

__device__ __forceinline__ uint32_t swoff(int row, int c) {
    return (uint32_t)(row * 64 + ((c ^ ((row >> 1) & 3)) << 4));
}

__device__ __forceinline__ float softplus_f(float v) {
    if (v > 20.f)  return v;
    if (v < -20.f) return __expf(v);
    return log1pf(__expf(v));
}

// ===========================================================================
// 128x128 NT GEMM, bf16 hi/lo split, 3-stage single-sync cp.async pipeline,
// 2 CTAs/SM. EPI: 0 = store, 1 = softplus(v+bias[col]) store,
//              2 = splitK slab: blockIdx.z = k-slice, C += z*sstride.
// ===========================================================================
#define GSTAGE 32768
#define GEMM_SMEM (3 * GSTAGE)

template <int EPI>
__global__ __launch_bounds__(256, 2) void gemm_mma(
    const __nv_bfloat16* __restrict__ Ah, const __nv_bfloat16* __restrict__ Al,
    const __nv_bfloat16* __restrict__ Bh, const __nv_bfloat16* __restrict__ Bl,
    float* __restrict__ C, const float* __restrict__ bias,
    int N, int Kc, int lda, int ldb, int ldc, int sstride)
{
    extern __shared__ char smem[];
    const uint32_t sb = smem_to_u32(smem);
    const int tid  = threadIdx.x;
    const int wid  = tid >> 5;
    const int lane = tid & 31;
    const int wm = wid & 1;
    const int wn = wid >> 1;
    const int row0 = blockIdx.y * 128;
    const int col0 = blockIdx.x * 128;
    const int kstart = (EPI == 2) ? blockIdx.z * Kc : 0;
    if (EPI == 2) C += (size_t)blockIdx.z * sstride;

    const int lr = tid >> 2;
    const int lc = tid & 3;

    const int a_rl = lane & 15;
    const int a_kc = lane >> 4;
    const int b_rl = (lane & 7) + ((lane >> 4) << 3);
    const int b_kc = (lane >> 3) & 1;

    float acc[4][4][4];
#pragma unroll
    for (int i = 0; i < 4; ++i)
#pragma unroll
        for (int j = 0; j < 4; ++j)
#pragma unroll
            for (int q = 0; q < 4; ++q) acc[i][j][q] = 0.f;

    const int nch = Kc >> 5;

    auto load_stage = [&](int stage, int k0) {
#pragma unroll
        for (int i = 0; i < 8; ++i) {
            const int tile = i >> 1;
            const int r = ((i & 1) << 6) + lr;
            const uint32_t dst = sb + stage * GSTAGE + tile * 8192 + swoff(r, lc);
            const __nv_bfloat16* src;
            if (tile < 2) {
                const __nv_bfloat16* base = tile ? Al : Ah;
                src = base + (size_t)(row0 + r) * lda + k0 + lc * 8;
            } else {
                int gn = col0 + r; if (gn >= N) gn = N - 1;
                const __nv_bfloat16* base = (tile == 2) ? Bh : Bl;
                src = base + (size_t)gn * ldb + k0 + lc * 8;
            }
            CP_ASYNC16(dst, src);
        }
    };

    // prologue: 2 of 3 stages in flight
    load_stage(0, kstart); CP_COMMIT();
    if (nch > 1) { load_stage(1, kstart + 32); CP_COMMIT(); }

    for (int ch = 0; ch < nch; ++ch) {
        if (ch < nch - 1) { CP_WAIT1(); } else { CP_WAIT0(); }
        __syncthreads();           // single barrier per chunk

        const uint32_t st = sb + (ch % 3) * GSTAGE;
#pragma unroll
        for (int ks = 0; ks < 2; ++ks) {
            uint32_t ah[4][4], al[4][4];
#pragma unroll
            for (int mt = 0; mt < 4; ++mt) {
                const int row = wm * 64 + mt * 16 + a_rl;
                const uint32_t ad = st + swoff(row, ks * 2 + a_kc);
                LDSM_X4(ah[mt][0], ah[mt][1], ah[mt][2], ah[mt][3], ad);
                LDSM_X4(al[mt][0], al[mt][1], al[mt][2], al[mt][3], ad + 8192);
            }
            uint32_t bh[2][4], bl[2][4];
#pragma unroll
            for (int p = 0; p < 2; ++p) {
                const int row = wn * 32 + p * 16 + b_rl;
                const uint32_t bd = st + 16384 + swoff(row, ks * 2 + b_kc);
                LDSM_X4(bh[p][0], bh[p][1], bh[p][2], bh[p][3], bd);
                LDSM_X4(bl[p][0], bl[p][1], bl[p][2], bl[p][3], bd + 8192);
            }
#pragma unroll
            for (int mt = 0; mt < 4; ++mt)
#pragma unroll
                for (int nt = 0; nt < 4; ++nt) {
                    uint32_t bfh[2] = { bh[nt >> 1][(nt & 1) * 2],
                                        bh[nt >> 1][(nt & 1) * 2 + 1] };
                    uint32_t bfl[2] = { bl[nt >> 1][(nt & 1) * 2],
                                        bl[nt >> 1][(nt & 1) * 2 + 1] };
                    MMA_BF16(acc[mt][nt], ah[mt], bfh);
                    MMA_BF16(acc[mt][nt], ah[mt], bfl);
                    MMA_BF16(acc[mt][nt], al[mt], bfh);
                }
        }
        if (ch + 2 < nch) {
            load_stage((ch + 2) % 3, kstart + ((ch + 2) << 5));
            CP_COMMIT();
        }
    }

#pragma unroll
    for (int mt = 0; mt < 4; ++mt) {
        const int r = row0 + wm * 64 + mt * 16 + (lane >> 2);
#pragma unroll
        for (int nt = 0; nt < 4; ++nt) {
            const int cb = col0 + wn * 32 + nt * 8 + ((lane & 3) << 1);
            if (cb >= N) continue;
            if (EPI == 1) {
                const float b0 = bias[cb], b1 = bias[cb + 1];
                *(float2*)(C + (size_t)r * ldc + cb) = make_float2(
                    softplus_f(acc[mt][nt][0] + b0), softplus_f(acc[mt][nt][1] + b1));
                *(float2*)(C + (size_t)(r + 8) * ldc + cb) = make_float2(
                    softplus_f(acc[mt][nt][2] + b0), softplus_f(acc[mt][nt][3] + b1));
            } else {
                *(float2*)(C + (size_t)r * ldc + cb) =
                    make_float2(acc[mt][nt][0], acc[mt][nt][1]);
                *(float2*)(C + (size_t)(r + 8) * ldc + cb) =
                    make_float2(acc[mt][nt][2], acc[mt][nt][3]);
            }
        }
    }
}

// ---------------------------------------------------------------------------
__global__ __launch_bounds__(256) void cvt_split(
    const float4* __restrict__ src, __nv_bfloat162* __restrict__ hi,
    __nv_bfloat162* __restrict__ lo, int n4)
{
    int i = blockIdx.x * blockDim.x + threadIdx.x;
    if (i >= n4) return;
    float4 v = src[i];
    __nv_bfloat16 h0 = __float2bfloat16(v.x), h1 = __float2bfloat16(v.y);
    __nv_bfloat16 h2 = __float2bfloat16(v.z), h3 = __float2bfloat16(v.w);
    hi[2 * i]     = __halves2bfloat162(h0, h1);
    hi[2 * i + 1] = __halves2bfloat162(h2, h3);
    lo[2 * i]     = __halves2bfloat162(
        __float2bfloat16(v.x - __bfloat162float(h0)),
        __float2bfloat16(v.y - __bfloat162float(h1)));
    lo[2 * i + 1] = __halves2bfloat162(
        __float2bfloat16(v.z - __bfloat162float(h2)),
        __float2bfloat16(v.w - __bfloat162float(h3)));
}

// sum NSLAB splitK slabs -> fp32 xdbl + bf16 hi/lo
__global__ __launch_bounds__(256) void reduce_split_kernel(
    const float4* __restrict__ slabs, float4* __restrict__ xdbl,
    __nv_bfloat162* __restrict__ hi, __nv_bfloat162* __restrict__ lo, int n4)
{
    int i = blockIdx.x * blockDim.x + threadIdx.x;
    if (i >= n4) return;
    float4 v = slabs[i];
#pragma unroll
    for (int s = 1; s < NSLAB; ++s) {
        float4 w = slabs[(size_t)s * n4 + i];
        v.x += w.x; v.y += w.y; v.z += w.z; v.w += w.w;
    }
    xdbl[i] = v;
    __nv_bfloat16 h0 = __float2bfloat16(v.x), h1 = __float2bfloat16(v.y);
    __nv_bfloat16 h2 = __float2bfloat16(v.z), h3 = __float2bfloat16(v.w);
    hi[2 * i]     = __halves2bfloat162(h0, h1);
    hi[2 * i + 1] = __halves2bfloat162(h2, h3);
    lo[2 * i]     = __halves2bfloat162(
        __float2bfloat16(v.x - __bfloat162float(h0)),
        __float2bfloat16(v.y - __bfloat162float(h1)));
    lo[2 * i + 1] = __halves2bfloat162(
        __float2bfloat16(v.z - __bfloat162float(h2)),
        __float2bfloat16(v.w - __bfloat162float(h3)));
}

// causal dwconv(4) + bias + SiLU, 2 channels/thread (float2) — ncu-verified.
__global__ __launch_bounds__(256) void conv_silu_kernel(
    const float* __restrict__ xr, const float* __restrict__ cw,
    const float* __restrict__ cb, float* __restrict__ u,
    __nv_bfloat162* __restrict__ uh, __nv_bfloat162* __restrict__ ul)
{
    int idx = blockIdx.x * blockDim.x + threadIdx.x;
    if (idx >= NTOK * DINNER / 2) return;
    int dp = idx & (DINNER / 2 - 1);
    int d  = dp << 1;
    int m  = idx >> 10;
    int b  = m >> 11;
    int l  = m & (LSEQ - 1);

    float4 w0 = *(const float4*)(cw + d * 4);
    float4 w1 = *(const float4*)(cw + d * 4 + 4);
    float2 a = make_float2(cb[d], cb[d + 1]);
    int base = b << 11;
    const float* p = xr + (size_t)(base + l) * 4096 + d;
    float2 t;
    if (l >= 3) { t = *(const float2*)(p - 3 * 4096);
                  a.x = fmaf(t.x, w0.x, a.x); a.y = fmaf(t.y, w1.x, a.y); }
    if (l >= 2) { t = *(const float2*)(p - 2 * 4096);
                  a.x = fmaf(t.x, w0.y, a.x); a.y = fmaf(t.y, w1.y, a.y); }
    if (l >= 1) { t = *(const float2*)(p - 1 * 4096);
                  a.x = fmaf(t.x, w0.z, a.x); a.y = fmaf(t.y, w1.z, a.y); }
    t = *(const float2*)p;
    a.x = fmaf(t.x, w0.w, a.x); a.y = fmaf(t.y, w1.w, a.y);

    float vx = a.x / (1.f + __expf(-a.x));
    float vy = a.y / (1.f + __expf(-a.y));
    *(float2*)(u + (size_t)idx * 2) = make_float2(vx, vy);
    __nv_bfloat16 hx = __float2bfloat16(vx), hy = __float2bfloat16(vy);
    uh[idx] = __halves2bfloat162(hx, hy);
    ul[idx] = __halves2bfloat162(
        __float2bfloat16(vx - __bfloat162float(hx)),
        __float2bfloat16(vy - __bfloat162float(hy)));
}

// ---------------------------------------------------------------------------
// Chunked parallel scan, one thread per (channel, chunk): 16 states in regs.
// idx layout for sA/sS/hc: (c<<16) | (ch<<4) | n.
// ---------------------------------------------------------------------------
__global__ __launch_bounds__(256) void scan_pass1(
    const float* __restrict__ delta, const float* __restrict__ u,
    const float* __restrict__ xdbl, const float* __restrict__ A_log,
    float* __restrict__ sA, float* __restrict__ sS)
{
    int gid = blockIdx.x * blockDim.x + threadIdx.x;   // 0..65535
    int ch = gid & 4095;
    int c  = gid >> 12;
    int b = ch >> 11, d = ch & (DINNER - 1);

    float A[DSTATE];
#pragma unroll
    for (int q = 0; q < 4; ++q) {
        float4 al4 = *(const float4*)(A_log + d * DSTATE + q * 4);
        A[q * 4 + 0] = -__expf(al4.x); A[q * 4 + 1] = -__expf(al4.y);
        A[q * 4 + 2] = -__expf(al4.z); A[q * 4 + 3] = -__expf(al4.w);
    }

    const size_t chanBase = (size_t)(b << 11) * DINNER + d;
    const float* dp = delta + chanBase;
    const float* up = u + chanBase;
    const float* xd = xdbl + (size_t)(b << 11) * XDBL;

    float a[DSTATE], h[DSTATE];
#pragma unroll
    for (int n = 0; n < DSTATE; ++n) { a[n] = 1.f; h[n] = 0.f; }

    const int l0 = c * CLEN;
    for (int i = 0; i < CLEN; ++i) {
        const int l = l0 + i;
        float dl = dp[(size_t)l * DINNER];
        float ul = up[(size_t)l * DINNER];
        const float* bp = xd + l * XDBL + DTRANK;
        float B[DSTATE];
#pragma unroll
        for (int q = 0; q < 4; ++q)
            *(float4*)(B + q * 4) = *(const float4*)(bp + q * 4);
        float du = dl * ul;
#pragma unroll
        for (int n = 0; n < DSTATE; ++n) {
            float dA = __expf(dl * A[n]);
            h[n] = fmaf(dA, h[n], du * B[n]);
            a[n] *= dA;
        }
    }
    const int base = (c << 16) | (ch << 4);
#pragma unroll
    for (int q = 0; q < 4; ++q) {
        *(float4*)(sA + base + q * 4) = *(const float4*)(a + q * 4);
        *(float4*)(sS + base + q * 4) = *(const float4*)(h + q * 4);
    }
}

__global__ __launch_bounds__(256) void scan_pass2(
    const float* __restrict__ sA, const float* __restrict__ sS,
    float* __restrict__ hcar)
{
    int gid = blockIdx.x * blockDim.x + threadIdx.x;   // (ch<<4)|n
    float hc = 0.f;
#pragma unroll
    for (int c = 0; c < NCH; ++c) {
        int idx = (c << 16) | gid;
        hcar[idx] = hc;
        hc = fmaf(sA[idx], hc, sS[idx]);
    }
}

__global__ __launch_bounds__(256) void scan_pass3(
    const float* __restrict__ delta, const float* __restrict__ u,
    const float* __restrict__ xdbl, const float* __restrict__ A_log,
    const float* __restrict__ hcar, float* __restrict__ ys)
{
    int gid = blockIdx.x * blockDim.x + threadIdx.x;   // 0..65535
    int ch = gid & 4095;
    int c  = gid >> 12;
    int b = ch >> 11, d = ch & (DINNER - 1);

    float A[DSTATE];
#pragma unroll
    for (int q = 0; q < 4; ++q) {
        float4 al4 = *(const float4*)(A_log + d * DSTATE + q * 4);
        A[q * 4 + 0] = -__expf(al4.x); A[q * 4 + 1] = -__expf(al4.y);
        A[q * 4 + 2] = -__expf(al4.z); A[q * 4 + 3] = -__expf(al4.w);
    }

    const size_t chanBase = (size_t)(b << 11) * DINNER + d;
    const float* dp = delta + chanBase;
    const float* up = u + chanBase;
    const float* xd = xdbl + (size_t)(b << 11) * XDBL;
    float* yp = ys + chanBase;

    float h[DSTATE];
    const int base = (c << 16) | (ch << 4);
#pragma unroll
    for (int q = 0; q < 4; ++q)
        *(float4*)(h + q * 4) = *(const float4*)(hcar + base + q * 4);

    const int l0 = c * CLEN;
    for (int i = 0; i < CLEN; ++i) {
        const int l = l0 + i;
        float dl = dp[(size_t)l * DINNER];
        float ul = up[(size_t)l * DINNER];
        const float* bp = xd + l * XDBL + DTRANK;
        float B[DSTATE], Cc[DSTATE];
#pragma unroll
        for (int q = 0; q < 4; ++q) {
            *(float4*)(B + q * 4)  = *(const float4*)(bp + q * 4);
            *(float4*)(Cc + q * 4) = *(const float4*)(bp + DSTATE + q * 4);
        }
        float du = dl * ul;
        float v = 0.f;
#pragma unroll
        for (int n = 0; n < DSTATE; ++n) {
            float dA = __expf(dl * A[n]);
            h[n] = fmaf(dA, h[n], du * B[n]);
            v = fmaf(h[n], Cc[n], v);
        }
        yp[(size_t)l * DINNER] = v;
    }
}

// y = (ys + u*D) * silu(res), 2 channels/thread; emits bf16 hi/lo.
__global__ __launch_bounds__(256) void gate_kernel(
    const float* __restrict__ ys, const float* __restrict__ u,
    const float* __restrict__ Dp, const float* __restrict__ xr,
    __nv_bfloat162* __restrict__ ygh, __nv_bfloat162* __restrict__ ygl)
{
    int idx = blockIdx.x * blockDim.x + threadIdx.x;
    if (idx >= NTOK * DINNER / 2) return;
    int dpair = idx & (DINNER / 2 - 1);
    int d = dpair << 1;
    int m = idx >> 10;
    float2 res = *(const float2*)(xr + (size_t)m * 4096 + DINNER + d);
    float2 yv  = *(const float2*)(ys + (size_t)idx * 2);
    float2 uv  = *(const float2*)(u + (size_t)idx * 2);
    float2 Dv  = *(const float2*)(Dp + d);
    float gx = res.x / (1.f + __expf(-res.x));
    float gy = res.y / (1.f + __expf(-res.y));
    float vx = (yv.x + uv.x * Dv.x) * gx;
    float vy = (yv.y + uv.y * Dv.y) * gy;
    __nv_bfloat16 hx = __float2bfloat16(vx), hy = __float2bfloat16(vy);
    ygh[idx] = __halves2bfloat162(hx, hy);
    ygl[idx] = __halves2bfloat162(
        __float2bfloat16(vx - __bfloat162float(hx)),
        __float2bfloat16(vy - __bfloat162float(hy)));
}

// ---------------------------------------------------------------------------
extern "C" void kernel_launch(void* const* d_in, const int* in_sizes, int n_in,
                              void* d_out, int out_size)
{
    const float* x        = (const float*)d_in[0];
    const float* conv_w   = (const float*)d_in[2];
    const float* conv_b   = (const float*)d_in[3];
    const float* dtproj_b = (const float*)d_in[6];
    const float* A_log    = (const float*)d_in[7];
    const float* Dvec     = (const float*)d_in[8];
    float* out            = (float*)d_out;

    float *xr, *u, *xdblp, *xdbl, *delta, *ys, *sA, *sS, *hc;
    cudaGetSymbolAddress((void**)&xr,    g_xr);
    cudaGetSymbolAddress((void**)&u,     g_u);
    cudaGetSymbolAddress((void**)&xdblp, g_xdblp);
    cudaGetSymbolAddress((void**)&xdbl,  g_xdbl);
    cudaGetSymbolAddress((void**)&delta, g_delta);
    cudaGetSymbolAddress((void**)&ys,    g_ys);
    cudaGetSymbolAddress((void**)&sA,    g_sA);
    cudaGetSymbolAddress((void**)&sS,    g_sS);
    cudaGetSymbolAddress((void**)&hc,    g_hc);

    __nv_bfloat16 *xh, *xl, *wih, *wil, *uh, *ul, *wxh, *wxl;
    __nv_bfloat16 *xdh, *xdl, *wdh, *wdl, *ygh, *ygl, *woh, *wol;
    cudaGetSymbolAddress((void**)&xh,  g_xh);  cudaGetSymbolAddress((void**)&xl,  g_xl);
    cudaGetSymbolAddress((void**)&wih, g_wih); cudaGetSymbolAddress((void**)&wil, g_wil);
    cudaGetSymbolAddress((void**)&uh,  g_uh);  cudaGetSymbolAddress((void**)&ul,  g_ul);
    cudaGetSymbolAddress((void**)&wxh, g_wxh); cudaGetSymbolAddress((void**)&wxl, g_wxl);
    cudaGetSymbolAddress((void**)&xdh, g_xdh); cudaGetSymbolAddress((void**)&xdl, g_xdl);
    cudaGetSymbolAddress((void**)&wdh, g_wdh); cudaGetSymbolAddress((void**)&wdl, g_wdl);
    cudaGetSymbolAddress((void**)&ygh, g_ygh); cudaGetSymbolAddress((void**)&ygl, g_ygl);
    cudaGetSymbolAddress((void**)&woh, g_woh); cudaGetSymbolAddress((void**)&wol, g_wol);

    cudaFuncSetAttribute(gemm_mma<0>, cudaFuncAttributeMaxDynamicSharedMemorySize, GEMM_SMEM);
    cudaFuncSetAttribute(gemm_mma<1>, cudaFuncAttributeMaxDynamicSharedMemorySize, GEMM_SMEM);
    cudaFuncSetAttribute(gemm_mma<2>, cudaFuncAttributeMaxDynamicSharedMemorySize, GEMM_SMEM);

    const int EW2 = NTOK * DINNER / 2;
#define CVT(src, hi, lo, n) \
    cvt_split<<<(n) / 1024, 256>>>((const float4*)(src), (__nv_bfloat162*)(hi), \
                                   (__nv_bfloat162*)(lo), (n) / 4)

    // launches 0-2: conversions — keeps in_proj gemm at profiled index 3
    CVT(x, xh, xl, NTOK * DMODEL);
    CVT(d_in[1], wih, wil, 4096 * DMODEL);
    CVT(d_in[4], wxh, wxl, XDBL * DINNER);
    // launch 3 (PROFILED): in_proj xr = x @ in_w^T  (4096 x 4096 x 1024)
    gemm_mma<0><<<dim3(32, 32), 256, GEMM_SMEM>>>(
        xh, xl, wih, wil, xr, nullptr, 4096, DMODEL, DMODEL, DMODEL, 4096, 0);
    // conv + silu -> u, uh, ul
    conv_silu_kernel<<<EW2 / 256, 256>>>(xr, conv_w, conv_b, u,
                                         (__nv_bfloat162*)uh, (__nv_bfloat162*)ul);
    // x_proj splitK(4) slabs (4096 x 96 x 2048), grid (1,32,NSLAB)
    gemm_mma<2><<<dim3(1, 32, NSLAB), 256, GEMM_SMEM>>>(
        uh, ul, wxh, wxl, xdblp, nullptr, XDBL, DINNER / NSLAB,
        DINNER, DINNER, XDBL, NTOK * XDBL);
    reduce_split_kernel<<<(NTOK * XDBL / 4 + 255) / 256, 256>>>(
        (const float4*)xdblp, (float4*)xdbl,
        (__nv_bfloat162*)xdh, (__nv_bfloat162*)xdl, NTOK * XDBL / 4);
    // dt_proj + bias + softplus: delta (4096 x 2048 x 64)
    CVT(d_in[5], wdh, wdl, DINNER * DTRANK);
    gemm_mma<1><<<dim3(16, 32), 256, GEMM_SMEM>>>(
        xdh, xdl, wdh, wdl, delta, dtproj_b, DINNER, DTRANK, XDBL, DTRANK, DINNER, 0);
    // chunked parallel scan (thread-per-channel-chunk)
    scan_pass1<<<(4096 * NCH) / 256, 256>>>(delta, u, xdbl, A_log, sA, sS);
    scan_pass2<<<(NTOK * DSTATE) / 256, 256>>>(sA, sS, hc);
    scan_pass3<<<(4096 * NCH) / 256, 256>>>(delta, u, xdbl, A_log, hc, ys);
    // gate -> ygh/ygl
    gate_kernel<<<EW2 / 256, 256>>>(ys, u, Dvec, xr,
                                    (__nv_bfloat162*)ygh, (__nv_bfloat162*)ygl);
    // out_proj DIRECT (256 CTAs = single wave at 2 CTAs/SM): (4096x1024x2048)
    CVT(d_in[9], woh, wol, DMODEL * DINNER);
    gemm_mma<0><<<dim3(8, 32), 256, GEMM_SMEM>>>(
        ygh, ygl, woh, wol, out, nullptr, DMODEL, DINNER, DINNER, DINNER, DMODEL, 0);
#undef CVT
}